// round 8
// baseline (speedup 1.0000x reference)
#include <cuda_runtime.h>
#include <cuda_bf16.h>
#include <cstdlib>

#define NN   50000
#define EE   800000
#define INF  128
#define HID  100
#define HIDP 104
#define OUTF 64
#define SCAN_T 1024

// -------- device scratch --------
__device__ float g_dinv[NN];
__device__ float g_hs1[NN * HID];   // (x@W1) * dinv[row]
__device__ float g_hs2[NN * OUTF];  // (h1@W2) * dinv[row]
__device__ int   g_cnt[NN];
__device__ int   g_off[NN];
__device__ int   g_cur[NN];
__device__ int   g_csrc[EE];
__device__ int   g_zero_idx[256];   // stays zero (warm-up indices)

// ---------------- CSR build ----------------
__global__ void k_zero_cnt() {
    int i = blockIdx.x * blockDim.x + threadIdx.x;
    if (i < NN) g_cnt[i] = 0;
}

__global__ void k_count(const int* __restrict__ dst, int ne) {
    int e = blockIdx.x * blockDim.x + threadIdx.x;
    if (e < ne) atomicAdd(&g_cnt[dst[e]], 1);
}

// single block: exclusive scan of g_cnt -> g_off/g_cur, dinv = rsqrt(cnt+1)
__global__ __launch_bounds__(SCAN_T) void k_scan() {
    __shared__ int ssum[SCAN_T];
    const int per = (NN + SCAN_T - 1) / SCAN_T;
    int t = threadIdx.x;
    int start = t * per;
    int end = min(start + per, NN);
    int sum = 0;
#pragma unroll 7
    for (int i = start; i < end; i++) sum += g_cnt[i];
    ssum[t] = sum;
    __syncthreads();
    for (int off = 1; off < SCAN_T; off <<= 1) {
        int v = (t >= off) ? ssum[t - off] : 0;
        __syncthreads();
        ssum[t] += v;
        __syncthreads();
    }
    int run = (t == 0) ? 0 : ssum[t - 1];
    for (int i = start; i < end; i++) {
        int c = g_cnt[i];
        g_off[i] = run;
        g_cur[i] = run;
        g_dinv[i] = rsqrtf((float)(c + 1));
        run += c;
    }
}

__global__ void k_fill(const int* __restrict__ src, const int* __restrict__ dst, int ne) {
    int e = blockIdx.x * blockDim.x + threadIdx.x;
    if (e < ne) {
        int pos = atomicAdd(&g_cur[dst[e]], 1);
        g_csrc[pos] = src[e];
    }
}

// ---------------- GEMM1: hs1 = (x @ W1) * dinv ----------------
__global__ __launch_bounds__(256) void k_gemm1(const float* __restrict__ x,
                                               const float* __restrict__ W1) {
    extern __shared__ float smem[];
    float* smW = smem;                 // 128*104
    float* smX = smem + INF * HIDP;    // 128*65

    const int tid = threadIdx.x;
    const int tx  = tid & 31;
    const int ty  = tid >> 5;
    const int row0 = blockIdx.x * 128;

    for (int i = tid; i < INF * HIDP; i += 256) {
        int k = i / HIDP, c = i - k * HIDP;
        smW[i] = (c < HID) ? W1[k * HID + c] : 0.0f;
    }

    float acc[4][13];
#pragma unroll
    for (int r = 0; r < 4; r++)
#pragma unroll
        for (int j = 0; j < 13; j++) acc[r][j] = 0.0f;

    const float4* x4 = (const float4*)x;
#pragma unroll
    for (int kc = 0; kc < 2; kc++) {
        __syncthreads();
        for (int i = tid; i < 128 * 16; i += 256) {
            int r = i >> 4, q = i & 15;
            int row = row0 + r;
            float4 v = make_float4(0.f, 0.f, 0.f, 0.f);
            if (row < NN) v = x4[row * (INF / 4) + kc * 16 + q];
            float* p = &smX[r * 65 + q * 4];
            p[0] = v.x; p[1] = v.y; p[2] = v.z; p[3] = v.w;
        }
        __syncthreads();

#pragma unroll 4
        for (int k = 0; k < 64; k++) {
            float xv0 = smX[(tx      ) * 65 + k];
            float xv1 = smX[(tx + 32 ) * 65 + k];
            float xv2 = smX[(tx + 64 ) * 65 + k];
            float xv3 = smX[(tx + 96 ) * 65 + k];
            const float* wrow = &smW[(kc * 64 + k) * HIDP + ty];
#pragma unroll
            for (int j = 0; j < 13; j++) {
                float wv = wrow[8 * j];
                acc[0][j] = fmaf(xv0, wv, acc[0][j]);
                acc[1][j] = fmaf(xv1, wv, acc[1][j]);
                acc[2][j] = fmaf(xv2, wv, acc[2][j]);
                acc[3][j] = fmaf(xv3, wv, acc[3][j]);
            }
        }
    }

#pragma unroll
    for (int r = 0; r < 4; r++) {
        int row = row0 + tx + 32 * r;
        if (row < NN) {
            float s = g_dinv[row];
#pragma unroll
            for (int j = 0; j < 13; j++) {
                int c = ty + 8 * j;
                if (c < HID) g_hs1[row * HID + c] = acc[r][j] * s;
            }
        }
    }
}

// ---------------- fused A: gather1 -> smH(relu) -> GEMM2 -> hs2 ----------------
// Block: 256 threads / 8 warps / 128 rows.
// Phase 1: warp w gathers rows w*16..w*16+15 into smH (lanes 0..24 own float4 chunks).
// Phase 2: classic smem GEMM vs W2, epilogue writes hs2 = result * dinv[row].
__global__ __launch_bounds__(256) void k_fused_a(const float4* __restrict__ hs,
                                                 const float* __restrict__ W2,
                                                 const float* __restrict__ b1) {
    extern __shared__ float smem[];
    float* smW = smem;                  // 100*64
    float* smH = smem + HID * OUTF;     // 128*101
    __shared__ float sb1[HID];

    const int tid = threadIdx.x;
    const int tx  = tid & 31;
    const int ty  = tid >> 5;
    const int row0 = blockIdx.x * 128;

    for (int i = tid; i < HID * OUTF; i += 256) smW[i] = W2[i];
    if (tid < HID) sb1[tid] = b1[tid];
    __syncthreads();

    // Phase 1: gather + relu into smH
    for (int rr = 0; rr < 16; rr++) {
        int r = ty * 16 + rr;
        int row = row0 + r;
        if (tx < 25) {
            float* p = &smH[r * 101 + tx * 4];
            if (row < NN) {
                float4 acc = __ldg(hs + (size_t)row * 25 + tx);   // self loop
                int base = g_off[row];
                int cnt  = g_cnt[row];
                int j = 0;
                for (; j + 4 <= cnt; j += 4) {
                    int s0 = __ldg(&g_csrc[base + j + 0]);
                    int s1 = __ldg(&g_csrc[base + j + 1]);
                    int s2 = __ldg(&g_csrc[base + j + 2]);
                    int s3 = __ldg(&g_csrc[base + j + 3]);
                    float4 v0 = __ldg(hs + (size_t)s0 * 25 + tx);
                    float4 v1 = __ldg(hs + (size_t)s1 * 25 + tx);
                    float4 v2 = __ldg(hs + (size_t)s2 * 25 + tx);
                    float4 v3 = __ldg(hs + (size_t)s3 * 25 + tx);
                    acc.x += (v0.x + v1.x) + (v2.x + v3.x);
                    acc.y += (v0.y + v1.y) + (v2.y + v3.y);
                    acc.z += (v0.z + v1.z) + (v2.z + v3.z);
                    acc.w += (v0.w + v1.w) + (v2.w + v3.w);
                }
                for (; j < cnt; j++) {
                    int s0 = __ldg(&g_csrc[base + j]);
                    float4 v0 = __ldg(hs + (size_t)s0 * 25 + tx);
                    acc.x += v0.x; acc.y += v0.y; acc.z += v0.z; acc.w += v0.w;
                }
                float s = g_dinv[row];
                p[0] = fmaxf(fmaf(acc.x, s, sb1[tx * 4 + 0]), 0.0f);
                p[1] = fmaxf(fmaf(acc.y, s, sb1[tx * 4 + 1]), 0.0f);
                p[2] = fmaxf(fmaf(acc.z, s, sb1[tx * 4 + 2]), 0.0f);
                p[3] = fmaxf(fmaf(acc.w, s, sb1[tx * 4 + 3]), 0.0f);
            } else {
                p[0] = 0.0f; p[1] = 0.0f; p[2] = 0.0f; p[3] = 0.0f;
            }
        }
    }
    __syncthreads();

    // Phase 2: GEMM2 (128 x 100 @ 100 x 64)
    float acc[4][8];
#pragma unroll
    for (int r = 0; r < 4; r++)
#pragma unroll
        for (int j = 0; j < 8; j++) acc[r][j] = 0.0f;

#pragma unroll 4
    for (int k = 0; k < HID; k++) {
        float xv0 = smH[(tx      ) * 101 + k];
        float xv1 = smH[(tx + 32 ) * 101 + k];
        float xv2 = smH[(tx + 64 ) * 101 + k];
        float xv3 = smH[(tx + 96 ) * 101 + k];
        const float* wrow = &smW[k * OUTF + ty];
#pragma unroll
        for (int j = 0; j < 8; j++) {
            float wv = wrow[8 * j];
            acc[0][j] = fmaf(xv0, wv, acc[0][j]);
            acc[1][j] = fmaf(xv1, wv, acc[1][j]);
            acc[2][j] = fmaf(xv2, wv, acc[2][j]);
            acc[3][j] = fmaf(xv3, wv, acc[3][j]);
        }
    }

#pragma unroll
    for (int r = 0; r < 4; r++) {
        int row = row0 + tx + 32 * r;
        if (row < NN) {
            float s = g_dinv[row];
#pragma unroll
            for (int j = 0; j < 8; j++)
                g_hs2[row * OUTF + ty + 8 * j] = acc[r][j] * s;
        }
    }
}

// ---------------- fused B: gather2 -> +b2 -> L2 normalize -> out ----------------
// 2 rows per warp; 16 lanes per row, one float4 each (64 floats).
__global__ __launch_bounds__(256) void k_fused_b(const float4* __restrict__ hs,
                                                 const float* __restrict__ b2,
                                                 float4* __restrict__ out) {
    int w = (blockIdx.x * blockDim.x + threadIdx.x) >> 5;
    int lane = threadIdx.x & 31;
    int row = w * 2 + (lane >> 4);
    int c = lane & 15;
    if (row >= NN) return;

    float4 acc = __ldg(hs + (size_t)row * 16 + c);      // self loop
    int base = g_off[row];
    int cnt  = g_cnt[row];
    int j = 0;
    for (; j + 4 <= cnt; j += 4) {
        int s0 = __ldg(&g_csrc[base + j + 0]);
        int s1 = __ldg(&g_csrc[base + j + 1]);
        int s2 = __ldg(&g_csrc[base + j + 2]);
        int s3 = __ldg(&g_csrc[base + j + 3]);
        float4 v0 = __ldg(hs + (size_t)s0 * 16 + c);
        float4 v1 = __ldg(hs + (size_t)s1 * 16 + c);
        float4 v2 = __ldg(hs + (size_t)s2 * 16 + c);
        float4 v3 = __ldg(hs + (size_t)s3 * 16 + c);
        acc.x += (v0.x + v1.x) + (v2.x + v3.x);
        acc.y += (v0.y + v1.y) + (v2.y + v3.y);
        acc.z += (v0.z + v1.z) + (v2.z + v3.z);
        acc.w += (v0.w + v1.w) + (v2.w + v3.w);
    }
    for (; j < cnt; j++) {
        int s0 = __ldg(&g_csrc[base + j]);
        float4 v0 = __ldg(hs + (size_t)s0 * 16 + c);
        acc.x += v0.x; acc.y += v0.y; acc.z += v0.z; acc.w += v0.w;
    }

    float s = g_dinv[row];
    float4 bb = __ldg((const float4*)b2 + c);
    float4 v;
    v.x = fmaf(acc.x, s, bb.x);
    v.y = fmaf(acc.y, s, bb.y);
    v.z = fmaf(acc.z, s, bb.z);
    v.w = fmaf(acc.w, s, bb.w);

    float ss = v.x * v.x + v.y * v.y + v.z * v.z + v.w * v.w;
#pragma unroll
    for (int o = 8; o > 0; o >>= 1) ss += __shfl_xor_sync(0xffffffffu, ss, o);
    float sc = 1.0f / fmaxf(sqrtf(ss), 1e-12f);
    v.x *= sc; v.y *= sc; v.z *= sc; v.w *= sc;
    out[(size_t)row * 16 + c] = v;
}

// ---------------- warm-up + device pointer cache ----------------
static const size_t kSmem1 = (size_t)(INF * HIDP + 128 * 65) * sizeof(float);   // 86528
static const size_t kSmemA = (size_t)(HID * OUTF + 128 * 101) * sizeof(float);  // 77312

static float* p_hs1 = nullptr;
static float* p_hs2 = nullptr;

namespace {
struct ModulePreload {
    ModulePreload() {
        setenv("CUDA_MODULE_LOADING", "EAGER", 1);
        cudaFuncSetAttribute(k_gemm1,  cudaFuncAttributeMaxDynamicSharedMemorySize, (int)kSmem1);
        cudaFuncSetAttribute(k_fused_a, cudaFuncAttributeMaxDynamicSharedMemorySize, (int)kSmemA);

        void *zi, *dv, *h1, *h2;
        cudaGetSymbolAddress(&zi, g_zero_idx);
        cudaGetSymbolAddress(&dv, g_dinv);
        cudaGetSymbolAddress(&h1, g_hs1);
        cudaGetSymbolAddress(&h2, g_hs2);
        p_hs1 = (float*)h1;
        p_hs2 = (float*)h2;

        const int*   zidx = (const int*)zi;
        const float* fh1  = (const float*)h1;
        const float* fdv  = (const float*)dv;

        // warm-up: one launch per kernel (commits module arena before checkpoint)
        k_zero_cnt<<<(NN + 255) / 256, 256>>>();
        k_count<<<1, 256>>>(zidx, 256);
        k_scan<<<1, SCAN_T>>>();
        k_fill<<<1, 256>>>(zidx, zidx, 256);
        k_zero_cnt<<<(NN + 255) / 256, 256>>>();   // reset state
        k_scan<<<1, SCAN_T>>>();
        k_gemm1<<<1, 256, kSmem1>>>(fh1, fh1);
        k_fused_a<<<1, 256, kSmemA>>>((const float4*)p_hs1, fh1, fdv);
        k_fused_b<<<1, 256>>>((const float4*)p_hs2, fdv, (float4*)p_hs1);
        cudaDeviceSynchronize();
    }
};
ModulePreload g_preload;
}  // namespace

// ---------------- host ----------------
extern "C" void kernel_launch(void* const* d_in, const int* in_sizes, int n_in,
                              void* d_out, int out_size) {
    const float* x   = (const float*)d_in[0];
    const int*   ei  = (const int*)d_in[1];     // [2, E]: src then dst
    const float* W1  = (const float*)d_in[2];
    const float* b1  = (const float*)d_in[3];
    const float* W2  = (const float*)d_in[4];
    const float* b2  = (const float*)d_in[5];
    float* out = (float*)d_out;
    const int* src = ei;
    const int* dst = ei + EE;

    // CSR build (also computes dinv)
    k_zero_cnt<<<(NN + 255) / 256, 256>>>();
    k_count<<<(EE + 255) / 256, 256>>>(dst, EE);
    k_scan<<<1, SCAN_T>>>();
    k_fill<<<(EE + 255) / 256, 256>>>(src, dst, EE);

    k_gemm1<<<(NN + 127) / 128, 256, kSmem1>>>(x, W1);
    k_fused_a<<<(NN + 127) / 128, 256, kSmemA>>>((const float4*)p_hs1, W2, b1);
    k_fused_b<<<((NN + 1) / 2 * 32 + 255) / 256, 256>>>((const float4*)p_hs2, b2, (float4*)out);
}

// round 9
// speedup vs baseline: 1.4555x; 1.4555x over previous
#include <cuda_runtime.h>
#include <cuda_bf16.h>
#include <cstdlib>

#define NN   50000
#define EE   800000
#define INF  128
#define HID  100
#define HIDP 104
#define OUTF 64
#define SB   512
#define NB   ((NN + SB - 1) / SB)   // 98

// -------- device scratch --------
__device__ float g_dinv[NN];
__device__ float g_hs1[NN * HID];   // (x@W1) * dinv[row]
__device__ float g_agg1[NN * HID];
__device__ float g_hs2[NN * OUTF];  // (h1@W2) * dinv[row]
__device__ int   g_cnt[NN];
__device__ int   g_off[NN];
__device__ int   g_cur[NN];
__device__ int   g_csrc[EE];
__device__ int   g_bsum[NB];
__device__ int   g_bpre[NB];
__device__ int   g_zero_idx[256];   // stays zero (warm-up indices)

// ---------------- CSR build ----------------
__global__ void k_zero_cnt() {
    int i = blockIdx.x * blockDim.x + threadIdx.x;
    if (i < NN) g_cnt[i] = 0;
}

__global__ void k_count(const int* __restrict__ dst, int ne) {
    int e = blockIdx.x * blockDim.x + threadIdx.x;
    if (e < ne) atomicAdd(&g_cnt[dst[e]], 1);
}

// per-block sums of g_cnt (grid NB, block SB)
__global__ __launch_bounds__(SB) void k_bsum() {
    __shared__ int sh[SB];
    int t = threadIdx.x;
    int i = blockIdx.x * SB + t;
    sh[t] = (i < NN) ? g_cnt[i] : 0;
    __syncthreads();
#pragma unroll
    for (int o = SB / 2; o > 0; o >>= 1) {
        if (t < o) sh[t] += sh[t + o];
        __syncthreads();
    }
    if (t == 0) g_bsum[blockIdx.x] = sh[0];
}

// exclusive scan of NB block sums (1 block, 128 threads)
__global__ __launch_bounds__(128) void k_bscan() {
    __shared__ int sh[128];
    int t = threadIdx.x;
    int v = (t < NB) ? g_bsum[t] : 0;
    sh[t] = v;
    __syncthreads();
#pragma unroll
    for (int o = 1; o < 128; o <<= 1) {
        int u = (t >= o) ? sh[t - o] : 0;
        __syncthreads();
        sh[t] += u;
        __syncthreads();
    }
    if (t < NB) g_bpre[t] = sh[t] - v;   // exclusive prefix
}

// per-block local exclusive scan + global prefix -> g_off/g_cur/dinv
__global__ __launch_bounds__(SB) void k_offsets() {
    __shared__ int sh[SB];
    int b = blockIdx.x, t = threadIdx.x;
    int i = b * SB + t;
    int c = (i < NN) ? g_cnt[i] : 0;
    sh[t] = c;
    __syncthreads();
#pragma unroll
    for (int o = 1; o < SB; o <<= 1) {
        int u = (t >= o) ? sh[t - o] : 0;
        __syncthreads();
        sh[t] += u;
        __syncthreads();
    }
    if (i < NN) {
        int off = g_bpre[b] + sh[t] - c;
        g_off[i] = off;
        g_cur[i] = off;
        g_dinv[i] = rsqrtf((float)(c + 1));
    }
}

__global__ void k_fill(const int* __restrict__ src, const int* __restrict__ dst, int ne) {
    int e = blockIdx.x * blockDim.x + threadIdx.x;
    if (e < ne) {
        int pos = atomicAdd(&g_cur[dst[e]], 1);
        g_csrc[pos] = src[e];
    }
}

// ---------------- GEMM1: hs1 = (x @ W1) * dinv ----------------
__global__ __launch_bounds__(256) void k_gemm1(const float* __restrict__ x,
                                               const float* __restrict__ W1) {
    extern __shared__ float smem[];
    float* smW = smem;                 // 128*104
    float* smX = smem + INF * HIDP;    // 128*65

    const int tid = threadIdx.x;
    const int tx  = tid & 31;
    const int ty  = tid >> 5;
    const int row0 = blockIdx.x * 128;

    for (int i = tid; i < INF * HIDP; i += 256) {
        int k = i / HIDP, c = i - k * HIDP;
        smW[i] = (c < HID) ? W1[k * HID + c] : 0.0f;
    }

    float acc[4][13];
#pragma unroll
    for (int r = 0; r < 4; r++)
#pragma unroll
        for (int j = 0; j < 13; j++) acc[r][j] = 0.0f;

    const float4* x4 = (const float4*)x;
#pragma unroll
    for (int kc = 0; kc < 2; kc++) {
        __syncthreads();
        for (int i = tid; i < 128 * 16; i += 256) {
            int r = i >> 4, q = i & 15;
            int row = row0 + r;
            float4 v = make_float4(0.f, 0.f, 0.f, 0.f);
            if (row < NN) v = x4[row * (INF / 4) + kc * 16 + q];
            float* p = &smX[r * 65 + q * 4];
            p[0] = v.x; p[1] = v.y; p[2] = v.z; p[3] = v.w;
        }
        __syncthreads();

#pragma unroll 4
        for (int k = 0; k < 64; k++) {
            float xv0 = smX[(tx      ) * 65 + k];
            float xv1 = smX[(tx + 32 ) * 65 + k];
            float xv2 = smX[(tx + 64 ) * 65 + k];
            float xv3 = smX[(tx + 96 ) * 65 + k];
            const float* wrow = &smW[(kc * 64 + k) * HIDP + ty];
#pragma unroll
            for (int j = 0; j < 13; j++) {
                float wv = wrow[8 * j];
                acc[0][j] = fmaf(xv0, wv, acc[0][j]);
                acc[1][j] = fmaf(xv1, wv, acc[1][j]);
                acc[2][j] = fmaf(xv2, wv, acc[2][j]);
                acc[3][j] = fmaf(xv3, wv, acc[3][j]);
            }
        }
    }

#pragma unroll
    for (int r = 0; r < 4; r++) {
        int row = row0 + tx + 32 * r;
        if (row < NN) {
            float s = g_dinv[row];
#pragma unroll
            for (int j = 0; j < 13; j++) {
                int c = ty + 8 * j;
                if (c < HID) g_hs1[row * HID + c] = acc[r][j] * s;
            }
        }
    }
}

#define ACC4(a, v) { a.x += v.x; a.y += v.y; a.z += v.z; a.w += v.w; }

// ---------------- gather1: agg1[r] = hs1[r] + sum_{s in N(r)} hs1[s] ----------------
// warp per row; lanes 0..24 each own a float4; 8/4/1-tier unroll for deep MLP.
__global__ __launch_bounds__(256) void k_gather100(const float4* __restrict__ hs,
                                                   float4* __restrict__ agg) {
    int row = (blockIdx.x * blockDim.x + threadIdx.x) >> 5;
    int lane = threadIdx.x & 31;
    if (row >= NN || lane >= 25) return;
    int base = g_off[row];
    int cnt  = g_cnt[row];

    float4 acc = __ldg(hs + (size_t)row * 25 + lane);   // self loop
    int j = 0;
    for (; j + 8 <= cnt; j += 8) {
        int s[8];
#pragma unroll
        for (int u = 0; u < 8; u++) s[u] = __ldg(&g_csrc[base + j + u]);
        float4 v[8];
#pragma unroll
        for (int u = 0; u < 8; u++) v[u] = __ldg(hs + (size_t)s[u] * 25 + lane);
#pragma unroll
        for (int u = 0; u < 8; u++) ACC4(acc, v[u]);
    }
    for (; j + 4 <= cnt; j += 4) {
        int s[4];
#pragma unroll
        for (int u = 0; u < 4; u++) s[u] = __ldg(&g_csrc[base + j + u]);
        float4 v[4];
#pragma unroll
        for (int u = 0; u < 4; u++) v[u] = __ldg(hs + (size_t)s[u] * 25 + lane);
#pragma unroll
        for (int u = 0; u < 4; u++) ACC4(acc, v[u]);
    }
    for (; j < cnt; j++) {
        int s0 = __ldg(&g_csrc[base + j]);
        float4 v0 = __ldg(hs + (size_t)s0 * 25 + lane);
        ACC4(acc, v0);
    }
    agg[(size_t)row * 25 + lane] = acc;
}

// ---------------- GEMM2: h1=relu(agg1*dinv+b1) tile -> hs2=(h1@W2)*dinv ----------------
__global__ __launch_bounds__(256) void k_gemm2(const float* __restrict__ W2,
                                               const float* __restrict__ b1) {
    extern __shared__ float smem[];
    float* smW = smem;                  // 100*64
    float* smH = smem + HID * OUTF;     // 128*101

    const int tid = threadIdx.x;
    const int tx  = tid & 31;
    const int ty  = tid >> 5;
    const int row0 = blockIdx.x * 128;

    for (int i = tid; i < HID * OUTF; i += 256) smW[i] = W2[i];

    for (int i = tid; i < 128 * HID; i += 256) {
        int r = i / HID, c = i - r * HID;
        int row = row0 + r;
        float v = 0.0f;
        if (row < NN) v = fmaxf(g_agg1[row * HID + c] * g_dinv[row] + b1[c], 0.0f);
        smH[r * 101 + c] = v;
    }
    __syncthreads();

    float acc[4][8];
#pragma unroll
    for (int r = 0; r < 4; r++)
#pragma unroll
        for (int j = 0; j < 8; j++) acc[r][j] = 0.0f;

#pragma unroll 4
    for (int k = 0; k < HID; k++) {
        float xv0 = smH[(tx      ) * 101 + k];
        float xv1 = smH[(tx + 32 ) * 101 + k];
        float xv2 = smH[(tx + 64 ) * 101 + k];
        float xv3 = smH[(tx + 96 ) * 101 + k];
        const float* wrow = &smW[k * OUTF + ty];
#pragma unroll
        for (int j = 0; j < 8; j++) {
            float wv = wrow[8 * j];
            acc[0][j] = fmaf(xv0, wv, acc[0][j]);
            acc[1][j] = fmaf(xv1, wv, acc[1][j]);
            acc[2][j] = fmaf(xv2, wv, acc[2][j]);
            acc[3][j] = fmaf(xv3, wv, acc[3][j]);
        }
    }

#pragma unroll
    for (int r = 0; r < 4; r++) {
        int row = row0 + tx + 32 * r;
        if (row < NN) {
            float s = g_dinv[row];
#pragma unroll
            for (int j = 0; j < 8; j++)
                g_hs2[row * OUTF + ty + 8 * j] = acc[r][j] * s;
        }
    }
}

// ---------------- fused B: gather2 -> +b2 -> L2 normalize -> out ----------------
// 2 rows per warp; 16 lanes per row, one float4 each; 8/4/1-tier unroll.
__global__ __launch_bounds__(256) void k_fused_b(const float4* __restrict__ hs,
                                                 const float* __restrict__ b2,
                                                 float4* __restrict__ out) {
    int w = (blockIdx.x * blockDim.x + threadIdx.x) >> 5;
    int lane = threadIdx.x & 31;
    int row = w * 2 + (lane >> 4);
    int c = lane & 15;
    if (row >= NN) return;

    float4 acc = __ldg(hs + (size_t)row * 16 + c);      // self loop
    int base = g_off[row];
    int cnt  = g_cnt[row];
    int j = 0;
    for (; j + 8 <= cnt; j += 8) {
        int s[8];
#pragma unroll
        for (int u = 0; u < 8; u++) s[u] = __ldg(&g_csrc[base + j + u]);
        float4 v[8];
#pragma unroll
        for (int u = 0; u < 8; u++) v[u] = __ldg(hs + (size_t)s[u] * 16 + c);
#pragma unroll
        for (int u = 0; u < 8; u++) ACC4(acc, v[u]);
    }
    for (; j + 4 <= cnt; j += 4) {
        int s[4];
#pragma unroll
        for (int u = 0; u < 4; u++) s[u] = __ldg(&g_csrc[base + j + u]);
        float4 v[4];
#pragma unroll
        for (int u = 0; u < 4; u++) v[u] = __ldg(hs + (size_t)s[u] * 16 + c);
#pragma unroll
        for (int u = 0; u < 4; u++) ACC4(acc, v[u]);
    }
    for (; j < cnt; j++) {
        int s0 = __ldg(&g_csrc[base + j]);
        float4 v0 = __ldg(hs + (size_t)s0 * 16 + c);
        ACC4(acc, v0);
    }

    float s = g_dinv[row];
    float4 bb = __ldg((const float4*)b2 + c);
    float4 v;
    v.x = fmaf(acc.x, s, bb.x);
    v.y = fmaf(acc.y, s, bb.y);
    v.z = fmaf(acc.z, s, bb.z);
    v.w = fmaf(acc.w, s, bb.w);

    float ss = v.x * v.x + v.y * v.y + v.z * v.z + v.w * v.w;
#pragma unroll
    for (int o = 8; o > 0; o >>= 1) ss += __shfl_xor_sync(0xffffffffu, ss, o);
    float sc = 1.0f / fmaxf(sqrtf(ss), 1e-12f);
    v.x *= sc; v.y *= sc; v.z *= sc; v.w *= sc;
    out[(size_t)row * 16 + c] = v;
}

// ---------------- warm-up + device pointer cache ----------------
static const size_t kSmem1 = (size_t)(INF * HIDP + 128 * 65) * sizeof(float);   // 86528
static const size_t kSmem2 = (size_t)(HID * OUTF + 128 * 101) * sizeof(float);  // 77312

static float* p_hs1  = nullptr;
static float* p_agg1 = nullptr;
static float* p_hs2  = nullptr;

namespace {
struct ModulePreload {
    ModulePreload() {
        setenv("CUDA_MODULE_LOADING", "EAGER", 1);
        cudaFuncSetAttribute(k_gemm1, cudaFuncAttributeMaxDynamicSharedMemorySize, (int)kSmem1);
        cudaFuncSetAttribute(k_gemm2, cudaFuncAttributeMaxDynamicSharedMemorySize, (int)kSmem2);

        void *zi, *dv, *h1, *h2, *a1;
        cudaGetSymbolAddress(&zi, g_zero_idx);
        cudaGetSymbolAddress(&dv, g_dinv);
        cudaGetSymbolAddress(&h1, g_hs1);
        cudaGetSymbolAddress(&h2, g_hs2);
        cudaGetSymbolAddress(&a1, g_agg1);
        p_hs1  = (float*)h1;
        p_agg1 = (float*)a1;
        p_hs2  = (float*)h2;

        const int*   zidx = (const int*)zi;
        const float* fh1  = (const float*)h1;
        const float* fdv  = (const float*)dv;

        // warm-up: one launch per kernel (commits module arena before checkpoint)
        k_zero_cnt<<<(NN + 255) / 256, 256>>>();
        k_count<<<1, 256>>>(zidx, 256);
        k_bsum<<<NB, SB>>>();
        k_bscan<<<1, 128>>>();
        k_offsets<<<NB, SB>>>();
        k_fill<<<1, 256>>>(zidx, zidx, 256);
        k_gemm1<<<1, 256, kSmem1>>>(fh1, fh1);
        k_gather100<<<1, 256>>>((const float4*)p_hs1, (float4*)p_agg1);
        k_gemm2<<<1, 256, kSmem2>>>(fh1, fdv);
        k_fused_b<<<1, 256>>>((const float4*)p_hs2, fdv, (float4*)p_hs1);
        cudaDeviceSynchronize();
    }
};
ModulePreload g_preload;
}  // namespace

// ---------------- host ----------------
extern "C" void kernel_launch(void* const* d_in, const int* in_sizes, int n_in,
                              void* d_out, int out_size) {
    const float* x   = (const float*)d_in[0];
    const int*   ei  = (const int*)d_in[1];     // [2, E]: src then dst
    const float* W1  = (const float*)d_in[2];
    const float* b1  = (const float*)d_in[3];
    const float* W2  = (const float*)d_in[4];
    const float* b2  = (const float*)d_in[5];
    float* out = (float*)d_out;
    const int* src = ei;
    const int* dst = ei + EE;

    // CSR build (parallel scan; also computes dinv)
    k_zero_cnt<<<(NN + 255) / 256, 256>>>();
    k_count<<<(EE + 255) / 256, 256>>>(dst, EE);
    k_bsum<<<NB, SB>>>();
    k_bscan<<<1, 128>>>();
    k_offsets<<<NB, SB>>>();
    k_fill<<<(EE + 255) / 256, 256>>>(src, dst, EE);

    k_gemm1<<<(NN + 127) / 128, 256, kSmem1>>>(x, W1);
    k_gather100<<<(NN * 32 + 255) / 256, 256>>>((const float4*)p_hs1, (float4*)p_agg1);

    k_gemm2<<<(NN + 127) / 128, 256, kSmem2>>>(W2, b1);
    k_fused_b<<<((NN + 1) / 2 * 32 + 255) / 256, 256>>>((const float4*)p_hs2, b2, (float4*)out);
}

// round 11
// speedup vs baseline: 1.4936x; 1.0262x over previous
#include <cuda_runtime.h>
#include <cuda_bf16.h>
#include <cstdlib>

#define NN   50000
#define EE   800000
#define INF  128
#define HID  100
#define HIDP 104
#define OUTF 64
#define SB   512
#define NB   ((NN + SB - 1) / SB)   // 98

// -------- device scratch --------
__device__ float g_dinv[NN];
__device__ float g_h1[NN * HID];    // x@W1 (RAW, unscaled)
__device__ float g_agg1[NN * HID];  // sum of dinv-scaled neighbors (incl self)
__device__ float g_hs2[NN * OUTF];  // (h1'@W2) * dinv[row]
__device__ int   g_cnt[NN];
__device__ int   g_off[NN];
__device__ int   g_cur[NN];
__device__ int   g_csrc[EE];
__device__ int   g_bsum[NB];
__device__ int   g_bpre[NB];
__device__ int   g_zero_idx[256];   // stays zero (warm-up indices)

// ---------------- CSR build ----------------
__global__ void k_zero_cnt() {
    int i = blockIdx.x * blockDim.x + threadIdx.x;
    if (i < NN) g_cnt[i] = 0;
}

__global__ void k_count(const int* __restrict__ dst, int ne) {
    int e = blockIdx.x * blockDim.x + threadIdx.x;
    if (e < ne) atomicAdd(&g_cnt[dst[e]], 1);
}

__global__ __launch_bounds__(SB) void k_bsum() {
    __shared__ int sh[SB];
    int t = threadIdx.x;
    int i = blockIdx.x * SB + t;
    sh[t] = (i < NN) ? g_cnt[i] : 0;
    __syncthreads();
#pragma unroll
    for (int o = SB / 2; o > 0; o >>= 1) {
        if (t < o) sh[t] += sh[t + o];
        __syncthreads();
    }
    if (t == 0) g_bsum[blockIdx.x] = sh[0];
}

__global__ __launch_bounds__(128) void k_bscan() {
    __shared__ int sh[128];
    int t = threadIdx.x;
    int v = (t < NB) ? g_bsum[t] : 0;
    sh[t] = v;
    __syncthreads();
#pragma unroll
    for (int o = 1; o < 128; o <<= 1) {
        int u = (t >= o) ? sh[t - o] : 0;
        __syncthreads();
        sh[t] += u;
        __syncthreads();
    }
    if (t < NB) g_bpre[t] = sh[t] - v;
}

__global__ __launch_bounds__(SB) void k_offsets() {
    __shared__ int sh[SB];
    int b = blockIdx.x, t = threadIdx.x;
    int i = b * SB + t;
    int c = (i < NN) ? g_cnt[i] : 0;
    sh[t] = c;
    __syncthreads();
#pragma unroll
    for (int o = 1; o < SB; o <<= 1) {
        int u = (t >= o) ? sh[t - o] : 0;
        __syncthreads();
        sh[t] += u;
        __syncthreads();
    }
    if (i < NN) {
        int off = g_bpre[b] + sh[t] - c;
        g_off[i] = off;
        g_cur[i] = off;
        g_dinv[i] = rsqrtf((float)(c + 1));
    }
}

__global__ void k_fill(const int* __restrict__ src, const int* __restrict__ dst, int ne) {
    int e = blockIdx.x * blockDim.x + threadIdx.x;
    if (e < ne) {
        int pos = atomicAdd(&g_cur[dst[e]], 1);
        g_csrc[pos] = src[e];
    }
}

// ---------------- GEMM1 (raw): h1 = x @ W1  (no dinv — independent of CSR) ----------
__global__ __launch_bounds__(256) void k_gemm1(const float* __restrict__ x,
                                               const float* __restrict__ W1) {
    extern __shared__ float smem[];
    float* smW = smem;                 // 128*104
    float* smX = smem + INF * HIDP;    // 128*65

    const int tid = threadIdx.x;
    const int tx  = tid & 31;
    const int ty  = tid >> 5;
    const int row0 = blockIdx.x * 128;

    for (int i = tid; i < INF * HIDP; i += 256) {
        int k = i / HIDP, c = i - k * HIDP;
        smW[i] = (c < HID) ? W1[k * HID + c] : 0.0f;
    }

    float acc[4][13];
#pragma unroll
    for (int r = 0; r < 4; r++)
#pragma unroll
        for (int j = 0; j < 13; j++) acc[r][j] = 0.0f;

    const float4* x4 = (const float4*)x;
#pragma unroll
    for (int kc = 0; kc < 2; kc++) {
        __syncthreads();
        for (int i = tid; i < 128 * 16; i += 256) {
            int r = i >> 4, q = i & 15;
            int row = row0 + r;
            float4 v = make_float4(0.f, 0.f, 0.f, 0.f);
            if (row < NN) v = x4[row * (INF / 4) + kc * 16 + q];
            float* p = &smX[r * 65 + q * 4];
            p[0] = v.x; p[1] = v.y; p[2] = v.z; p[3] = v.w;
        }
        __syncthreads();

#pragma unroll 4
        for (int k = 0; k < 64; k++) {
            float xv0 = smX[(tx      ) * 65 + k];
            float xv1 = smX[(tx + 32 ) * 65 + k];
            float xv2 = smX[(tx + 64 ) * 65 + k];
            float xv3 = smX[(tx + 96 ) * 65 + k];
            const float* wrow = &smW[(kc * 64 + k) * HIDP + ty];
#pragma unroll
            for (int j = 0; j < 13; j++) {
                float wv = wrow[8 * j];
                acc[0][j] = fmaf(xv0, wv, acc[0][j]);
                acc[1][j] = fmaf(xv1, wv, acc[1][j]);
                acc[2][j] = fmaf(xv2, wv, acc[2][j]);
                acc[3][j] = fmaf(xv3, wv, acc[3][j]);
            }
        }
    }

#pragma unroll
    for (int r = 0; r < 4; r++) {
        int row = row0 + tx + 32 * r;
        if (row < NN) {
#pragma unroll
            for (int j = 0; j < 13; j++) {
                int c = ty + 8 * j;
                if (c < HID) g_h1[row * HID + c] = acc[r][j];
            }
        }
    }
}

#define FMA4(a, v, s) { a.x = fmaf(v.x, s, a.x); a.y = fmaf(v.y, s, a.y); \
                        a.z = fmaf(v.z, s, a.z); a.w = fmaf(v.w, s, a.w); }

// ---------------- gather1: agg1[r] = dinv[r]*h1[r] + sum dinv[s]*h1[s] ----------------
// warp per row; lanes 0..24 each own a float4; 8/4/1-tier unroll; per-edge dinv
// load is warp-uniform (broadcast) and accumulation uses FFMA (same pipe as FADD).
__global__ __launch_bounds__(256) void k_gather100(const float4* __restrict__ h,
                                                   float4* __restrict__ agg) {
    int row = (blockIdx.x * blockDim.x + threadIdx.x) >> 5;
    int lane = threadIdx.x & 31;
    if (row >= NN || lane >= 25) return;
    int base = g_off[row];
    int cnt  = g_cnt[row];

    float4 vr = __ldg(h + (size_t)row * 25 + lane);     // self loop
    float dvr = g_dinv[row];
    float4 acc = make_float4(vr.x * dvr, vr.y * dvr, vr.z * dvr, vr.w * dvr);

    int j = 0;
    for (; j + 8 <= cnt; j += 8) {
        int s[8];
#pragma unroll
        for (int u = 0; u < 8; u++) s[u] = __ldg(&g_csrc[base + j + u]);
        float4 v[8];
        float dv[8];
#pragma unroll
        for (int u = 0; u < 8; u++) { v[u] = __ldg(h + (size_t)s[u] * 25 + lane); dv[u] = __ldg(&g_dinv[s[u]]); }
#pragma unroll
        for (int u = 0; u < 8; u++) FMA4(acc, v[u], dv[u]);
    }
    for (; j + 4 <= cnt; j += 4) {
        int s[4];
#pragma unroll
        for (int u = 0; u < 4; u++) s[u] = __ldg(&g_csrc[base + j + u]);
        float4 v[4];
        float dv[4];
#pragma unroll
        for (int u = 0; u < 4; u++) { v[u] = __ldg(h + (size_t)s[u] * 25 + lane); dv[u] = __ldg(&g_dinv[s[u]]); }
#pragma unroll
        for (int u = 0; u < 4; u++) FMA4(acc, v[u], dv[u]);
    }
    for (; j < cnt; j++) {
        int s0 = __ldg(&g_csrc[base + j]);
        float4 v0 = __ldg(h + (size_t)s0 * 25 + lane);
        float dv0 = __ldg(&g_dinv[s0]);
        FMA4(acc, v0, dv0);
    }
    agg[(size_t)row * 25 + lane] = acc;
}

// ---------------- GEMM2: h1'=relu(agg1*dinv+b1) tile -> hs2=(h1'@W2)*dinv ----------------
__global__ __launch_bounds__(256) void k_gemm2(const float* __restrict__ W2,
                                               const float* __restrict__ b1) {
    extern __shared__ float smem[];
    float* smW = smem;                  // 100*64
    float* smH = smem + HID * OUTF;     // 128*101

    const int tid = threadIdx.x;
    const int tx  = tid & 31;
    const int ty  = tid >> 5;
    const int row0 = blockIdx.x * 128;

    for (int i = tid; i < HID * OUTF; i += 256) smW[i] = W2[i];

    for (int i = tid; i < 128 * HID; i += 256) {
        int r = i / HID, c = i - r * HID;
        int row = row0 + r;
        float v = 0.0f;
        if (row < NN) v = fmaxf(g_agg1[row * HID + c] * g_dinv[row] + b1[c], 0.0f);
        smH[r * 101 + c] = v;
    }
    __syncthreads();

    float acc[4][8];
#pragma unroll
    for (int r = 0; r < 4; r++)
#pragma unroll
        for (int j = 0; j < 8; j++) acc[r][j] = 0.0f;

#pragma unroll 4
    for (int k = 0; k < HID; k++) {
        float xv0 = smH[(tx      ) * 101 + k];
        float xv1 = smH[(tx + 32 ) * 101 + k];
        float xv2 = smH[(tx + 64 ) * 101 + k];
        float xv3 = smH[(tx + 96 ) * 101 + k];
        const float* wrow = &smW[k * OUTF + ty];
#pragma unroll
        for (int j = 0; j < 8; j++) {
            float wv = wrow[8 * j];
            acc[0][j] = fmaf(xv0, wv, acc[0][j]);
            acc[1][j] = fmaf(xv1, wv, acc[1][j]);
            acc[2][j] = fmaf(xv2, wv, acc[2][j]);
            acc[3][j] = fmaf(xv3, wv, acc[3][j]);
        }
    }

#pragma unroll
    for (int r = 0; r < 4; r++) {
        int row = row0 + tx + 32 * r;
        if (row < NN) {
            float s = g_dinv[row];
#pragma unroll
            for (int j = 0; j < 8; j++)
                g_hs2[row * OUTF + ty + 8 * j] = acc[r][j] * s;
        }
    }
}

#define ACC4(a, v) { a.x += v.x; a.y += v.y; a.z += v.z; a.w += v.w; }

// ---------------- fused B: gather2 -> +b2 -> L2 normalize -> out ----------------
__global__ __launch_bounds__(256) void k_fused_b(const float4* __restrict__ hs,
                                                 const float* __restrict__ b2,
                                                 float4* __restrict__ out) {
    int w = (blockIdx.x * blockDim.x + threadIdx.x) >> 5;
    int lane = threadIdx.x & 31;
    int row = w * 2 + (lane >> 4);
    int c = lane & 15;
    if (row >= NN) return;

    float4 acc = __ldg(hs + (size_t)row * 16 + c);      // self loop (pre-scaled)
    int base = g_off[row];
    int cnt  = g_cnt[row];
    int j = 0;
    for (; j + 8 <= cnt; j += 8) {
        int s[8];
#pragma unroll
        for (int u = 0; u < 8; u++) s[u] = __ldg(&g_csrc[base + j + u]);
        float4 v[8];
#pragma unroll
        for (int u = 0; u < 8; u++) v[u] = __ldg(hs + (size_t)s[u] * 16 + c);
#pragma unroll
        for (int u = 0; u < 8; u++) ACC4(acc, v[u]);
    }
    for (; j + 4 <= cnt; j += 4) {
        int s[4];
#pragma unroll
        for (int u = 0; u < 4; u++) s[u] = __ldg(&g_csrc[base + j + u]);
        float4 v[4];
#pragma unroll
        for (int u = 0; u < 4; u++) v[u] = __ldg(hs + (size_t)s[u] * 16 + c);
#pragma unroll
        for (int u = 0; u < 4; u++) ACC4(acc, v[u]);
    }
    for (; j < cnt; j++) {
        int s0 = __ldg(&g_csrc[base + j]);
        float4 v0 = __ldg(hs + (size_t)s0 * 16 + c);
        ACC4(acc, v0);
    }

    float s = g_dinv[row];
    float4 bb = __ldg((const float4*)b2 + c);
    float4 v;
    v.x = fmaf(acc.x, s, bb.x);
    v.y = fmaf(acc.y, s, bb.y);
    v.z = fmaf(acc.z, s, bb.z);
    v.w = fmaf(acc.w, s, bb.w);

    float ss = v.x * v.x + v.y * v.y + v.z * v.z + v.w * v.w;
#pragma unroll
    for (int o = 8; o > 0; o >>= 1) ss += __shfl_xor_sync(0xffffffffu, ss, o);
    float sc = 1.0f / fmaxf(sqrtf(ss), 1e-12f);
    v.x *= sc; v.y *= sc; v.z *= sc; v.w *= sc;
    out[(size_t)row * 16 + c] = v;
}

// ---------------- warm-up + device pointer cache + fork resources ----------------
static const size_t kSmem1 = (size_t)(INF * HIDP + 128 * 65) * sizeof(float);   // 86528
static const size_t kSmem2 = (size_t)(HID * OUTF + 128 * 101) * sizeof(float);  // 77312

static float* p_h1   = nullptr;
static float* p_agg1 = nullptr;
static float* p_hs2  = nullptr;
static cudaStream_t s1;
static cudaEvent_t ev_fork, ev_join;

namespace {
struct ModulePreload {
    ModulePreload() {
        setenv("CUDA_MODULE_LOADING", "EAGER", 1);
        cudaFuncSetAttribute(k_gemm1, cudaFuncAttributeMaxDynamicSharedMemorySize, (int)kSmem1);
        cudaFuncSetAttribute(k_gemm2, cudaFuncAttributeMaxDynamicSharedMemorySize, (int)kSmem2);

        cudaStreamCreateWithFlags(&s1, cudaStreamNonBlocking);
        cudaEventCreateWithFlags(&ev_fork, cudaEventDisableTiming);
        cudaEventCreateWithFlags(&ev_join, cudaEventDisableTiming);

        void *zi, *dv, *h1, *h2, *a1;
        cudaGetSymbolAddress(&zi, g_zero_idx);
        cudaGetSymbolAddress(&dv, g_dinv);
        cudaGetSymbolAddress(&h1, g_h1);
        cudaGetSymbolAddress(&h2, g_hs2);
        cudaGetSymbolAddress(&a1, g_agg1);
        p_h1   = (float*)h1;
        p_agg1 = (float*)a1;
        p_hs2  = (float*)h2;

        const int*   zidx = (const int*)zi;
        const float* fh1  = (const float*)h1;
        const float* fdv  = (const float*)dv;

        // warm-up: one launch per kernel (commits module arena before checkpoint)
        k_zero_cnt<<<(NN + 255) / 256, 256>>>();
        k_count<<<1, 256>>>(zidx, 256);
        k_bsum<<<NB, SB>>>();
        k_bscan<<<1, 128>>>();
        k_offsets<<<NB, SB>>>();
        k_fill<<<1, 256>>>(zidx, zidx, 256);
        k_gemm1<<<1, 256, kSmem1, s1>>>(fh1, fh1);   // also warms s1
        k_gather100<<<1, 256>>>((const float4*)p_h1, (float4*)p_agg1);
        k_gemm2<<<1, 256, kSmem2>>>(fh1, fdv);
        k_fused_b<<<1, 256>>>((const float4*)p_hs2, fdv, (float4*)p_h1);
        cudaDeviceSynchronize();
    }
};
ModulePreload g_preload;
}  // namespace

// ---------------- host ----------------
extern "C" void kernel_launch(void* const* d_in, const int* in_sizes, int n_in,
                              void* d_out, int out_size) {
    const float* x   = (const float*)d_in[0];
    const int*   ei  = (const int*)d_in[1];     // [2, E]: src then dst
    const float* W1  = (const float*)d_in[2];
    const float* b1  = (const float*)d_in[3];
    const float* W2  = (const float*)d_in[4];
    const float* b2  = (const float*)d_in[5];
    float* out = (float*)d_out;
    const int* src = ei;
    const int* dst = ei + EE;

    // Fork: GEMM1 (independent of CSR) on s1, CSR build on the capture stream.
    cudaEventRecord(ev_fork, 0);
    cudaStreamWaitEvent(s1, ev_fork, 0);
    k_gemm1<<<(NN + 127) / 128, 256, kSmem1, s1>>>(x, W1);
    cudaEventRecord(ev_join, s1);

    k_zero_cnt<<<(NN + 255) / 256, 256>>>();
    k_count<<<(EE + 255) / 256, 256>>>(dst, EE);
    k_bsum<<<NB, SB>>>();
    k_bscan<<<1, 128>>>();
    k_offsets<<<NB, SB>>>();
    k_fill<<<(EE + 255) / 256, 256>>>(src, dst, EE);

    // Join: gather needs h1 + CSR + dinv.
    cudaStreamWaitEvent(0, ev_join, 0);
    k_gather100<<<(NN * 32 + 255) / 256, 256>>>((const float4*)p_h1, (float4*)p_agg1);

    k_gemm2<<<(NN + 127) / 128, 256, kSmem2>>>(W2, b1);
    k_fused_b<<<((NN + 1) / 2 * 32 + 255) / 256, 256>>>((const float4*)p_hs2, b2, (float4*)out);
}

// round 12
// speedup vs baseline: 1.9958x; 1.3362x over previous
#include <cuda_runtime.h>
#include <cuda_fp16.h>
#include <cstdlib>

#define NN   50000
#define EE   800000
#define INF  128
#define HID  100
#define HIDP 104
#define OUTF 64
#define SB   512
#define NB   ((NN + SB - 1) / SB)   // 98

// -------- device scratch --------
__device__ float        g_dinv[NN];
__device__ unsigned int g_h1u[NN * 50];    // h1 = x@W1, fp16 pairs (100 halves/row)
__device__ float        g_agg1[NN * HID];  // fp32 aggregated layer-1
__device__ unsigned int g_hs2u[NN * 32];   // hs2 = (h1'@W2)*dinv, fp16 pairs (64 halves/row)
__device__ int          g_cnt[NN];
__device__ int          g_off[NN];
__device__ int          g_cur[NN];
__device__ int          g_csrc[EE];
__device__ int          g_bsum[NB];
__device__ int          g_bpre[NB];
__device__ int          g_zero_idx[256];   // stays zero (warm-up indices)

// ---------------- CSR build ----------------
__global__ void k_zero_cnt() {
    int i = blockIdx.x * blockDim.x + threadIdx.x;
    if (i < NN) g_cnt[i] = 0;
}

__global__ void k_count(const int* __restrict__ dst, int ne) {
    int e = blockIdx.x * blockDim.x + threadIdx.x;
    if (e < ne) atomicAdd(&g_cnt[dst[e]], 1);
}

__global__ __launch_bounds__(SB) void k_bsum() {
    __shared__ int sh[SB];
    int t = threadIdx.x;
    int i = blockIdx.x * SB + t;
    sh[t] = (i < NN) ? g_cnt[i] : 0;
    __syncthreads();
#pragma unroll
    for (int o = SB / 2; o > 0; o >>= 1) {
        if (t < o) sh[t] += sh[t + o];
        __syncthreads();
    }
    if (t == 0) g_bsum[blockIdx.x] = sh[0];
}

__global__ __launch_bounds__(128) void k_bscan() {
    __shared__ int sh[128];
    int t = threadIdx.x;
    int v = (t < NB) ? g_bsum[t] : 0;
    sh[t] = v;
    __syncthreads();
#pragma unroll
    for (int o = 1; o < 128; o <<= 1) {
        int u = (t >= o) ? sh[t - o] : 0;
        __syncthreads();
        sh[t] += u;
        __syncthreads();
    }
    if (t < NB) g_bpre[t] = sh[t] - v;
}

__global__ __launch_bounds__(SB) void k_offsets() {
    __shared__ int sh[SB];
    int b = blockIdx.x, t = threadIdx.x;
    int i = b * SB + t;
    int c = (i < NN) ? g_cnt[i] : 0;
    sh[t] = c;
    __syncthreads();
#pragma unroll
    for (int o = 1; o < SB; o <<= 1) {
        int u = (t >= o) ? sh[t - o] : 0;
        __syncthreads();
        sh[t] += u;
        __syncthreads();
    }
    if (i < NN) {
        int off = g_bpre[b] + sh[t] - c;
        g_off[i] = off;
        g_cur[i] = off;
        g_dinv[i] = rsqrtf((float)(c + 1));
    }
}

__global__ void k_fill(const int* __restrict__ src, const int* __restrict__ dst, int ne) {
    int e = blockIdx.x * blockDim.x + threadIdx.x;
    if (e < ne) {
        int pos = atomicAdd(&g_cur[dst[e]], 1);
        g_csrc[pos] = src[e];
    }
}

// ---------------- GEMM1: h1 = x @ W1 -> fp16, coalesced via smem staging ----------
__global__ __launch_bounds__(256) void k_gemm1(const float* __restrict__ x,
                                               const float* __restrict__ W1) {
    extern __shared__ float smem[];
    float* smW = smem;                 // 128*104
    float* smX = smem + INF * HIDP;    // 128*65 floats (reused as half staging)

    const int tid = threadIdx.x;
    const int tx  = tid & 31;
    const int ty  = tid >> 5;
    const int row0 = blockIdx.x * 128;

    for (int i = tid; i < INF * HIDP; i += 256) {
        int k = i / HIDP, c = i - k * HIDP;
        smW[i] = (c < HID) ? W1[k * HID + c] : 0.0f;
    }

    float acc[4][13];
#pragma unroll
    for (int r = 0; r < 4; r++)
#pragma unroll
        for (int j = 0; j < 13; j++) acc[r][j] = 0.0f;

    const float4* x4 = (const float4*)x;
#pragma unroll
    for (int kc = 0; kc < 2; kc++) {
        __syncthreads();
        for (int i = tid; i < 128 * 16; i += 256) {
            int r = i >> 4, q = i & 15;
            int row = row0 + r;
            float4 v = make_float4(0.f, 0.f, 0.f, 0.f);
            if (row < NN) v = x4[row * (INF / 4) + kc * 16 + q];
            float* p = &smX[r * 65 + q * 4];
            p[0] = v.x; p[1] = v.y; p[2] = v.z; p[3] = v.w;
        }
        __syncthreads();

#pragma unroll 4
        for (int k = 0; k < 64; k++) {
            float xv0 = smX[(tx      ) * 65 + k];
            float xv1 = smX[(tx + 32 ) * 65 + k];
            float xv2 = smX[(tx + 64 ) * 65 + k];
            float xv3 = smX[(tx + 96 ) * 65 + k];
            const float* wrow = &smW[(kc * 64 + k) * HIDP + ty];
#pragma unroll
            for (int j = 0; j < 13; j++) {
                float wv = wrow[8 * j];
                acc[0][j] = fmaf(xv0, wv, acc[0][j]);
                acc[1][j] = fmaf(xv1, wv, acc[1][j]);
                acc[2][j] = fmaf(xv2, wv, acc[2][j]);
                acc[3][j] = fmaf(xv3, wv, acc[3][j]);
            }
        }
    }

    // Epilogue: stage fp16 tile in smem (reuse smX), then coalesced uint writes.
    __syncthreads();
    __half* hb = (__half*)smX;         // 128 x 104 halves (26.6 KB, fits 33 KB)
#pragma unroll
    for (int r = 0; r < 4; r++) {
        int rr = tx + 32 * r;
#pragma unroll
        for (int j = 0; j < 13; j++)
            hb[rr * 104 + ty + 8 * j] = __float2half(acc[r][j]);
    }
    __syncthreads();
    const unsigned int* hbu = (const unsigned int*)smX;   // 128 x 52 uints
    for (int i = tid; i < 128 * 50; i += 256) {
        int r = i / 50, q = i - r * 50;
        int row = row0 + r;
        if (row < NN) g_h1u[row * 50 + q] = hbu[r * 52 + q];
    }
}

// ---------------- gather1: agg1[r] = dinv[r]*h1[r] + sum dinv[s]*h1[s] (fp16 in) ------
// warp per row; lanes 0..24 each own one uint2 (4 halves); 8/4/1-tier unroll.
#define H2FMA(accA, accB, u2, s) {                                   \
    float2 _a = __half22float2(*(__half2*)&(u2).x);                  \
    float2 _b = __half22float2(*(__half2*)&(u2).y);                  \
    accA.x = fmaf(_a.x, s, accA.x); accA.y = fmaf(_a.y, s, accA.y);  \
    accB.x = fmaf(_b.x, s, accB.x); accB.y = fmaf(_b.y, s, accB.y); }

__global__ __launch_bounds__(256) void k_gather100(const uint2* __restrict__ h,
                                                   float4* __restrict__ agg) {
    int row = (blockIdx.x * blockDim.x + threadIdx.x) >> 5;
    int lane = threadIdx.x & 31;
    if (row >= NN || lane >= 25) return;
    int base = g_off[row];
    int cnt  = g_cnt[row];

    float2 aA = make_float2(0.f, 0.f), aB = make_float2(0.f, 0.f);
    {
        uint2 rv = __ldg(h + (size_t)row * 25 + lane);
        float dvr = g_dinv[row];
        H2FMA(aA, aB, rv, dvr);
    }
    int j = 0;
    for (; j + 8 <= cnt; j += 8) {
        int s[8];
#pragma unroll
        for (int u = 0; u < 8; u++) s[u] = __ldg(&g_csrc[base + j + u]);
        uint2 v[8]; float dv[8];
#pragma unroll
        for (int u = 0; u < 8; u++) { v[u] = __ldg(h + (size_t)s[u] * 25 + lane); dv[u] = __ldg(&g_dinv[s[u]]); }
#pragma unroll
        for (int u = 0; u < 8; u++) H2FMA(aA, aB, v[u], dv[u]);
    }
    for (; j + 4 <= cnt; j += 4) {
        int s[4];
#pragma unroll
        for (int u = 0; u < 4; u++) s[u] = __ldg(&g_csrc[base + j + u]);
        uint2 v[4]; float dv[4];
#pragma unroll
        for (int u = 0; u < 4; u++) { v[u] = __ldg(h + (size_t)s[u] * 25 + lane); dv[u] = __ldg(&g_dinv[s[u]]); }
#pragma unroll
        for (int u = 0; u < 4; u++) H2FMA(aA, aB, v[u], dv[u]);
    }
    for (; j < cnt; j++) {
        int s0 = __ldg(&g_csrc[base + j]);
        uint2 v0 = __ldg(h + (size_t)s0 * 25 + lane);
        float dv0 = __ldg(&g_dinv[s0]);
        H2FMA(aA, aB, v0, dv0);
    }
    agg[(size_t)row * 25 + lane] = make_float4(aA.x, aA.y, aB.x, aB.y);
}

// ---------------- GEMM2: h1'=relu(agg1*dinv+b1) -> hs2=(h1'@W2)*dinv (fp16 out) -------
__global__ __launch_bounds__(256) void k_gemm2(const float* __restrict__ W2,
                                               const float* __restrict__ b1) {
    extern __shared__ float smem[];
    float* smW = smem;                  // 100*64
    float* smH = smem + HID * OUTF;     // 128*101 (reused as half staging)

    const int tid = threadIdx.x;
    const int tx  = tid & 31;
    const int ty  = tid >> 5;
    const int row0 = blockIdx.x * 128;

    for (int i = tid; i < HID * OUTF; i += 256) smW[i] = W2[i];

    for (int i = tid; i < 128 * HID; i += 256) {
        int r = i / HID, c = i - r * HID;
        int row = row0 + r;
        float v = 0.0f;
        if (row < NN) v = fmaxf(g_agg1[row * HID + c] * g_dinv[row] + b1[c], 0.0f);
        smH[r * 101 + c] = v;
    }
    __syncthreads();

    float acc[4][8];
#pragma unroll
    for (int r = 0; r < 4; r++)
#pragma unroll
        for (int j = 0; j < 8; j++) acc[r][j] = 0.0f;

#pragma unroll 4
    for (int k = 0; k < HID; k++) {
        float xv0 = smH[(tx      ) * 101 + k];
        float xv1 = smH[(tx + 32 ) * 101 + k];
        float xv2 = smH[(tx + 64 ) * 101 + k];
        float xv3 = smH[(tx + 96 ) * 101 + k];
        const float* wrow = &smW[k * OUTF + ty];
#pragma unroll
        for (int j = 0; j < 8; j++) {
            float wv = wrow[8 * j];
            acc[0][j] = fmaf(xv0, wv, acc[0][j]);
            acc[1][j] = fmaf(xv1, wv, acc[1][j]);
            acc[2][j] = fmaf(xv2, wv, acc[2][j]);
            acc[3][j] = fmaf(xv3, wv, acc[3][j]);
        }
    }

    // Epilogue: fp16 staging in smem (reuse smH), coalesced uint writes.
    __syncthreads();
    __half* hb = (__half*)smH;          // 128 x 66 halves
#pragma unroll
    for (int r = 0; r < 4; r++) {
        int rr = tx + 32 * r;
        int row = row0 + rr;
        float s = (row < NN) ? g_dinv[row] : 0.0f;
#pragma unroll
        for (int j = 0; j < 8; j++)
            hb[rr * 66 + ty + 8 * j] = __float2half(acc[r][j] * s);
    }
    __syncthreads();
    const unsigned int* hbu = (const unsigned int*)smH;   // 128 x 33 uints
    for (int i = tid; i < 128 * 32; i += 256) {
        int r = i >> 5, q = i & 31;
        int row = row0 + r;
        if (row < NN) g_hs2u[row * 32 + q] = hbu[r * 33 + q];
    }
}

// ---------------- fused B: gather2(fp16) -> +b2 -> L2 normalize -> out ----------------
#define H2ADD(accA, accB, u2) {                                      \
    float2 _a = __half22float2(*(__half2*)&(u2).x);                  \
    float2 _b = __half22float2(*(__half2*)&(u2).y);                  \
    accA.x += _a.x; accA.y += _a.y; accB.x += _b.x; accB.y += _b.y; }

__global__ __launch_bounds__(256) void k_fused_b(const uint2* __restrict__ hs,
                                                 const float* __restrict__ b2,
                                                 float4* __restrict__ out) {
    int w = (blockIdx.x * blockDim.x + threadIdx.x) >> 5;
    int lane = threadIdx.x & 31;
    int row = w * 2 + (lane >> 4);
    int c = lane & 15;
    if (row >= NN) return;

    float2 aA, aB;
    {
        uint2 rv = __ldg(hs + (size_t)row * 16 + c);     // self loop (pre-scaled)
        float2 _a = __half22float2(*(__half2*)&rv.x);
        float2 _b = __half22float2(*(__half2*)&rv.y);
        aA = _a; aB = _b;
    }
    int base = g_off[row];
    int cnt  = g_cnt[row];
    int j = 0;
    for (; j + 8 <= cnt; j += 8) {
        int s[8];
#pragma unroll
        for (int u = 0; u < 8; u++) s[u] = __ldg(&g_csrc[base + j + u]);
        uint2 v[8];
#pragma unroll
        for (int u = 0; u < 8; u++) v[u] = __ldg(hs + (size_t)s[u] * 16 + c);
#pragma unroll
        for (int u = 0; u < 8; u++) H2ADD(aA, aB, v[u]);
    }
    for (; j + 4 <= cnt; j += 4) {
        int s[4];
#pragma unroll
        for (int u = 0; u < 4; u++) s[u] = __ldg(&g_csrc[base + j + u]);
        uint2 v[4];
#pragma unroll
        for (int u = 0; u < 4; u++) v[u] = __ldg(hs + (size_t)s[u] * 16 + c);
#pragma unroll
        for (int u = 0; u < 4; u++) H2ADD(aA, aB, v[u]);
    }
    for (; j < cnt; j++) {
        int s0 = __ldg(&g_csrc[base + j]);
        uint2 v0 = __ldg(hs + (size_t)s0 * 16 + c);
        H2ADD(aA, aB, v0);
    }

    float s = g_dinv[row];
    float4 bb = __ldg((const float4*)b2 + c);
    float4 v;
    v.x = fmaf(aA.x, s, bb.x);
    v.y = fmaf(aA.y, s, bb.y);
    v.z = fmaf(aB.x, s, bb.z);
    v.w = fmaf(aB.y, s, bb.w);

    float ss = v.x * v.x + v.y * v.y + v.z * v.z + v.w * v.w;
#pragma unroll
    for (int o = 8; o > 0; o >>= 1) ss += __shfl_xor_sync(0xffffffffu, ss, o);
    float sc = 1.0f / fmaxf(sqrtf(ss), 1e-12f);
    v.x *= sc; v.y *= sc; v.z *= sc; v.w *= sc;
    out[(size_t)row * 16 + c] = v;
}

// ---------------- warm-up + device pointer cache + fork resources ----------------
static const size_t kSmem1 = (size_t)(INF * HIDP + 128 * 65) * sizeof(float);   // 86528
static const size_t kSmem2 = (size_t)(HID * OUTF + 128 * 101) * sizeof(float);  // 77312

static unsigned int* p_h1u  = nullptr;
static float*        p_agg1 = nullptr;
static unsigned int* p_hs2u = nullptr;
static cudaStream_t s1;
static cudaEvent_t ev_fork, ev_join;

namespace {
struct ModulePreload {
    ModulePreload() {
        setenv("CUDA_MODULE_LOADING", "EAGER", 1);
        cudaFuncSetAttribute(k_gemm1, cudaFuncAttributeMaxDynamicSharedMemorySize, (int)kSmem1);
        cudaFuncSetAttribute(k_gemm2, cudaFuncAttributeMaxDynamicSharedMemorySize, (int)kSmem2);

        cudaStreamCreateWithFlags(&s1, cudaStreamNonBlocking);
        cudaEventCreateWithFlags(&ev_fork, cudaEventDisableTiming);
        cudaEventCreateWithFlags(&ev_join, cudaEventDisableTiming);

        void *zi, *dv, *h1, *h2, *a1;
        cudaGetSymbolAddress(&zi, g_zero_idx);
        cudaGetSymbolAddress(&dv, g_dinv);
        cudaGetSymbolAddress(&h1, g_h1u);
        cudaGetSymbolAddress(&h2, g_hs2u);
        cudaGetSymbolAddress(&a1, g_agg1);
        p_h1u  = (unsigned int*)h1;
        p_agg1 = (float*)a1;
        p_hs2u = (unsigned int*)h2;

        const int*   zidx = (const int*)zi;
        const float* fa1  = (const float*)a1;
        const float* fdv  = (const float*)dv;

        // warm-up: one launch per kernel (commits module arena before checkpoint)
        k_zero_cnt<<<(NN + 255) / 256, 256>>>();
        k_count<<<1, 256>>>(zidx, 256);
        k_bsum<<<NB, SB>>>();
        k_bscan<<<1, 128>>>();
        k_offsets<<<NB, SB>>>();
        k_fill<<<1, 256>>>(zidx, zidx, 256);
        k_gemm1<<<1, 256, kSmem1, s1>>>(fa1, fa1);   // also warms s1
        k_gather100<<<1, 256>>>((const uint2*)p_h1u, (float4*)p_agg1);
        k_gemm2<<<1, 256, kSmem2>>>(fa1, fdv);
        k_fused_b<<<1, 256>>>((const uint2*)p_hs2u, fdv, (float4*)p_agg1);
        cudaDeviceSynchronize();
    }
};
ModulePreload g_preload;
}  // namespace

// ---------------- host ----------------
extern "C" void kernel_launch(void* const* d_in, const int* in_sizes, int n_in,
                              void* d_out, int out_size) {
    const float* x   = (const float*)d_in[0];
    const int*   ei  = (const int*)d_in[1];     // [2, E]: src then dst
    const float* W1  = (const float*)d_in[2];
    const float* b1  = (const float*)d_in[3];
    const float* W2  = (const float*)d_in[4];
    const float* b2  = (const float*)d_in[5];
    float* out = (float*)d_out;
    const int* src = ei;
    const int* dst = ei + EE;

    // Fork: GEMM1 (independent of CSR) on s1, CSR build on the capture stream.
    cudaEventRecord(ev_fork, 0);
    cudaStreamWaitEvent(s1, ev_fork, 0);
    k_gemm1<<<(NN + 127) / 128, 256, kSmem1, s1>>>(x, W1);
    cudaEventRecord(ev_join, s1);

    k_zero_cnt<<<(NN + 255) / 256, 256>>>();
    k_count<<<(EE + 255) / 256, 256>>>(dst, EE);
    k_bsum<<<NB, SB>>>();
    k_bscan<<<1, 128>>>();
    k_offsets<<<NB, SB>>>();
    k_fill<<<(EE + 255) / 256, 256>>>(src, dst, EE);

    // Join: gather needs h1 + CSR + dinv.
    cudaStreamWaitEvent(0, ev_join, 0);
    k_gather100<<<(NN * 32 + 255) / 256, 256>>>((const uint2*)p_h1u, (float4*)p_agg1);

    k_gemm2<<<(NN + 127) / 128, 256, kSmem2>>>(W2, b1);
    k_fused_b<<<((NN + 1) / 2 * 32 + 255) / 256, 256>>>((const uint2*)p_hs2u, b2, (float4*)out);
}

// round 13
// speedup vs baseline: 2.2338x; 1.1192x over previous
#include <cuda_runtime.h>
#include <cuda_fp16.h>
#include <cstdlib>

#define NN   50000
#define EE   800000
#define INF  128
#define HID  100
#define HIDP 104
#define OUTF 64
#define SB   512
#define NB   ((NN + SB - 1) / SB)   // 98
#define CHA  25088                  // chunk-A rows (196 blocks of 128)

// -------- device scratch --------
__device__ float        g_dinv[NN];
__device__ unsigned int g_h1u[NN * 50];    // h1 = x@W1 (raw), fp16 pairs
__device__ uint2        g_a1p[NN * 25];    // h1' = relu(agg*dinv+b1), fp16 (100 halves/row)
__device__ unsigned int g_hs2u[NN * 32];   // hs2 = (h1'@W2)*dinv, fp16 pairs
__device__ int          g_cnt[NN];
__device__ int          g_off[NN];
__device__ int          g_cur[NN];
__device__ int          g_csrc[EE];
__device__ int          g_bsum[NB];
__device__ int          g_bpre[NB];
__device__ int          g_zero_idx[256];   // stays zero (warm-up indices)

// ---------------- CSR build ----------------
__global__ void k_zero_cnt() {
    int i = blockIdx.x * blockDim.x + threadIdx.x;
    if (i < NN) g_cnt[i] = 0;
}

__global__ void k_count(const int* __restrict__ dst, int ne) {
    int e = blockIdx.x * blockDim.x + threadIdx.x;
    if (e < ne) atomicAdd(&g_cnt[dst[e]], 1);
}

__global__ __launch_bounds__(SB) void k_bsum() {
    __shared__ int sh[SB];
    int t = threadIdx.x;
    int i = blockIdx.x * SB + t;
    sh[t] = (i < NN) ? g_cnt[i] : 0;
    __syncthreads();
#pragma unroll
    for (int o = SB / 2; o > 0; o >>= 1) {
        if (t < o) sh[t] += sh[t + o];
        __syncthreads();
    }
    if (t == 0) g_bsum[blockIdx.x] = sh[0];
}

__global__ __launch_bounds__(128) void k_bscan() {
    __shared__ int sh[128];
    int t = threadIdx.x;
    int v = (t < NB) ? g_bsum[t] : 0;
    sh[t] = v;
    __syncthreads();
#pragma unroll
    for (int o = 1; o < 128; o <<= 1) {
        int u = (t >= o) ? sh[t - o] : 0;
        __syncthreads();
        sh[t] += u;
        __syncthreads();
    }
    if (t < NB) g_bpre[t] = sh[t] - v;
}

__global__ __launch_bounds__(SB) void k_offsets() {
    __shared__ int sh[SB];
    int b = blockIdx.x, t = threadIdx.x;
    int i = b * SB + t;
    int c = (i < NN) ? g_cnt[i] : 0;
    sh[t] = c;
    __syncthreads();
#pragma unroll
    for (int o = 1; o < SB; o <<= 1) {
        int u = (t >= o) ? sh[t - o] : 0;
        __syncthreads();
        sh[t] += u;
        __syncthreads();
    }
    if (i < NN) {
        int off = g_bpre[b] + sh[t] - c;
        g_off[i] = off;
        g_cur[i] = off;
        g_dinv[i] = rsqrtf((float)(c + 1));
    }
}

__global__ void k_fill(const int* __restrict__ src, const int* __restrict__ dst, int ne) {
    int e = blockIdx.x * blockDim.x + threadIdx.x;
    if (e < ne) {
        int pos = atomicAdd(&g_cur[dst[e]], 1);
        g_csrc[pos] = src[e];
    }
}

// ---------------- GEMM1: h1 = x @ W1 -> fp16 (raw; CSR-independent) ----------
__global__ __launch_bounds__(256) void k_gemm1(const float* __restrict__ x,
                                               const float* __restrict__ W1) {
    extern __shared__ float smem[];
    float* smW = smem;                 // 128*104
    float* smX = smem + INF * HIDP;    // 128*65 floats (reused as half staging)

    const int tid = threadIdx.x;
    const int tx  = tid & 31;
    const int ty  = tid >> 5;
    const int row0 = blockIdx.x * 128;

    for (int i = tid; i < INF * HIDP; i += 256) {
        int k = i / HIDP, c = i - k * HIDP;
        smW[i] = (c < HID) ? W1[k * HID + c] : 0.0f;
    }

    float acc[4][13];
#pragma unroll
    for (int r = 0; r < 4; r++)
#pragma unroll
        for (int j = 0; j < 13; j++) acc[r][j] = 0.0f;

    const float4* x4 = (const float4*)x;
#pragma unroll
    for (int kc = 0; kc < 2; kc++) {
        __syncthreads();
        for (int i = tid; i < 128 * 16; i += 256) {
            int r = i >> 4, q = i & 15;
            int row = row0 + r;
            float4 v = make_float4(0.f, 0.f, 0.f, 0.f);
            if (row < NN) v = x4[row * (INF / 4) + kc * 16 + q];
            float* p = &smX[r * 65 + q * 4];
            p[0] = v.x; p[1] = v.y; p[2] = v.z; p[3] = v.w;
        }
        __syncthreads();

#pragma unroll 4
        for (int k = 0; k < 64; k++) {
            float xv0 = smX[(tx      ) * 65 + k];
            float xv1 = smX[(tx + 32 ) * 65 + k];
            float xv2 = smX[(tx + 64 ) * 65 + k];
            float xv3 = smX[(tx + 96 ) * 65 + k];
            const float* wrow = &smW[(kc * 64 + k) * HIDP + ty];
#pragma unroll
            for (int j = 0; j < 13; j++) {
                float wv = wrow[8 * j];
                acc[0][j] = fmaf(xv0, wv, acc[0][j]);
                acc[1][j] = fmaf(xv1, wv, acc[1][j]);
                acc[2][j] = fmaf(xv2, wv, acc[2][j]);
                acc[3][j] = fmaf(xv3, wv, acc[3][j]);
            }
        }
    }

    // Epilogue: fp16 staging in smem, coalesced uint writes.
    __syncthreads();
    __half* hb = (__half*)smX;         // 128 x 104 halves
#pragma unroll
    for (int r = 0; r < 4; r++) {
        int rr = tx + 32 * r;
#pragma unroll
        for (int j = 0; j < 13; j++)
            hb[rr * 104 + ty + 8 * j] = __float2half(acc[r][j]);
    }
    __syncthreads();
    const unsigned int* hbu = (const unsigned int*)smX;   // 128 x 52 uints
    for (int i = tid; i < 128 * 50; i += 256) {
        int r = i / 50, q = i - r * 50;
        int row = row0 + r;
        if (row < NN) g_h1u[row * 50 + q] = hbu[r * 52 + q];
    }
}

// ------- gather1: h1'[r] = relu((dinv[r]*h1[r] + sum dinv[s]*h1[s]) + b1) -> fp16 -------
// rows [r0, rend); warp per row; lanes 0..24 own one uint2 (4 halves); 8/4/1 unroll.
#define H2FMA(accA, accB, u2, s) {                                   \
    float2 _a = __half22float2(*(__half2*)&(u2).x);                  \
    float2 _b = __half22float2(*(__half2*)&(u2).y);                  \
    accA.x = fmaf(_a.x, s, accA.x); accA.y = fmaf(_a.y, s, accA.y);  \
    accB.x = fmaf(_b.x, s, accB.x); accB.y = fmaf(_b.y, s, accB.y); }

__global__ __launch_bounds__(256) void k_gather100(const uint2* __restrict__ h,
                                                   uint2* __restrict__ a1p,
                                                   const float* __restrict__ b1,
                                                   int r0, int rend) {
    int row = r0 + ((blockIdx.x * blockDim.x + threadIdx.x) >> 5);
    int lane = threadIdx.x & 31;
    if (row >= rend || lane >= 25) return;
    int base = g_off[row];
    int cnt  = g_cnt[row];

    float2 aA = make_float2(0.f, 0.f), aB = make_float2(0.f, 0.f);
    float dvr = g_dinv[row];
    {
        uint2 rv = __ldg(h + (size_t)row * 25 + lane);
        H2FMA(aA, aB, rv, dvr);
    }
    int j = 0;
    for (; j + 8 <= cnt; j += 8) {
        int s[8];
#pragma unroll
        for (int u = 0; u < 8; u++) s[u] = __ldg(&g_csrc[base + j + u]);
        uint2 v[8]; float dv[8];
#pragma unroll
        for (int u = 0; u < 8; u++) { v[u] = __ldg(h + (size_t)s[u] * 25 + lane); dv[u] = __ldg(&g_dinv[s[u]]); }
#pragma unroll
        for (int u = 0; u < 8; u++) H2FMA(aA, aB, v[u], dv[u]);
    }
    for (; j + 4 <= cnt; j += 4) {
        int s[4];
#pragma unroll
        for (int u = 0; u < 4; u++) s[u] = __ldg(&g_csrc[base + j + u]);
        uint2 v[4]; float dv[4];
#pragma unroll
        for (int u = 0; u < 4; u++) { v[u] = __ldg(h + (size_t)s[u] * 25 + lane); dv[u] = __ldg(&g_dinv[s[u]]); }
#pragma unroll
        for (int u = 0; u < 4; u++) H2FMA(aA, aB, v[u], dv[u]);
    }
    for (; j < cnt; j++) {
        int s0 = __ldg(&g_csrc[base + j]);
        uint2 v0 = __ldg(h + (size_t)s0 * 25 + lane);
        float dv0 = __ldg(&g_dinv[s0]);
        H2FMA(aA, aB, v0, dv0);
    }

    // layer-1 epilogue: * dinv[row] + b1, relu, fp16 pack
    float4 bb = __ldg((const float4*)b1 + lane);
    __half2 h0 = __floats2half2_rn(fmaxf(fmaf(aA.x, dvr, bb.x), 0.0f),
                                   fmaxf(fmaf(aA.y, dvr, bb.y), 0.0f));
    __half2 h1v = __floats2half2_rn(fmaxf(fmaf(aB.x, dvr, bb.z), 0.0f),
                                    fmaxf(fmaf(aB.y, dvr, bb.w), 0.0f));
    uint2 o;
    o.x = *(unsigned int*)&h0;
    o.y = *(unsigned int*)&h1v;
    a1p[(size_t)row * 25 + lane] = o;
}

// ---------------- GEMM2: hs2 = (h1' @ W2) * dinv -> fp16; rows [row0base...) -------
__global__ __launch_bounds__(256) void k_gemm2(const uint2* __restrict__ a1p,
                                               const float* __restrict__ W2,
                                               int row0base) {
    extern __shared__ float smem[];
    float* smW = smem;                  // 100*64
    float* smH = smem + HID * OUTF;     // 128*101 (reused as half staging)

    const int tid = threadIdx.x;
    const int tx  = tid & 31;
    const int ty  = tid >> 5;
    const int row0 = row0base + blockIdx.x * 128;

    for (int i = tid; i < HID * OUTF; i += 256) smW[i] = W2[i];

    // tile build: fp16 h1' -> fp32 smH
    for (int i = tid; i < 128 * 25; i += 256) {
        int r = i / 25, q = i - r * 25;
        int row = row0 + r;
        float* p = &smH[r * 101 + q * 4];
        if (row < NN) {
            uint2 u = __ldg(a1p + (size_t)row * 25 + q);
            float2 a = __half22float2(*(__half2*)&u.x);
            float2 b = __half22float2(*(__half2*)&u.y);
            p[0] = a.x; p[1] = a.y; p[2] = b.x; p[3] = b.y;
        } else {
            p[0] = 0.f; p[1] = 0.f; p[2] = 0.f; p[3] = 0.f;
        }
    }
    __syncthreads();

    float acc[4][8];
#pragma unroll
    for (int r = 0; r < 4; r++)
#pragma unroll
        for (int j = 0; j < 8; j++) acc[r][j] = 0.0f;

#pragma unroll 4
    for (int k = 0; k < HID; k++) {
        float xv0 = smH[(tx      ) * 101 + k];
        float xv1 = smH[(tx + 32 ) * 101 + k];
        float xv2 = smH[(tx + 64 ) * 101 + k];
        float xv3 = smH[(tx + 96 ) * 101 + k];
        const float* wrow = &smW[k * OUTF + ty];
#pragma unroll
        for (int j = 0; j < 8; j++) {
            float wv = wrow[8 * j];
            acc[0][j] = fmaf(xv0, wv, acc[0][j]);
            acc[1][j] = fmaf(xv1, wv, acc[1][j]);
            acc[2][j] = fmaf(xv2, wv, acc[2][j]);
            acc[3][j] = fmaf(xv3, wv, acc[3][j]);
        }
    }

    // Epilogue: *dinv, fp16 staging, coalesced writes.
    __syncthreads();
    __half* hb = (__half*)smH;          // 128 x 66 halves
#pragma unroll
    for (int r = 0; r < 4; r++) {
        int rr = tx + 32 * r;
        int row = row0 + rr;
        float s = (row < NN) ? g_dinv[row] : 0.0f;
#pragma unroll
        for (int j = 0; j < 8; j++)
            hb[rr * 66 + ty + 8 * j] = __float2half(acc[r][j] * s);
    }
    __syncthreads();
    const unsigned int* hbu = (const unsigned int*)smH;   // 128 x 33 uints
    for (int i = tid; i < 128 * 32; i += 256) {
        int r = i >> 5, q = i & 31;
        int row = row0 + r;
        if (row < NN) g_hs2u[row * 32 + q] = hbu[r * 33 + q];
    }
}

// ---------------- fused B: gather2(fp16) -> +b2 -> L2 normalize -> out ----------------
#define H2ADD(accA, accB, u2) {                                      \
    float2 _a = __half22float2(*(__half2*)&(u2).x);                  \
    float2 _b = __half22float2(*(__half2*)&(u2).y);                  \
    accA.x += _a.x; accA.y += _a.y; accB.x += _b.x; accB.y += _b.y; }

__global__ __launch_bounds__(256) void k_fused_b(const uint2* __restrict__ hs,
                                                 const float* __restrict__ b2,
                                                 float4* __restrict__ out) {
    int w = (blockIdx.x * blockDim.x + threadIdx.x) >> 5;
    int lane = threadIdx.x & 31;
    int row = w * 2 + (lane >> 4);
    int c = lane & 15;
    if (row >= NN) return;

    float2 aA, aB;
    {
        uint2 rv = __ldg(hs + (size_t)row * 16 + c);     // self loop (pre-scaled)
        aA = __half22float2(*(__half2*)&rv.x);
        aB = __half22float2(*(__half2*)&rv.y);
    }
    int base = g_off[row];
    int cnt  = g_cnt[row];
    int j = 0;
    for (; j + 8 <= cnt; j += 8) {
        int s[8];
#pragma unroll
        for (int u = 0; u < 8; u++) s[u] = __ldg(&g_csrc[base + j + u]);
        uint2 v[8];
#pragma unroll
        for (int u = 0; u < 8; u++) v[u] = __ldg(hs + (size_t)s[u] * 16 + c);
#pragma unroll
        for (int u = 0; u < 8; u++) H2ADD(aA, aB, v[u]);
    }
    for (; j + 4 <= cnt; j += 4) {
        int s[4];
#pragma unroll
        for (int u = 0; u < 4; u++) s[u] = __ldg(&g_csrc[base + j + u]);
        uint2 v[4];
#pragma unroll
        for (int u = 0; u < 4; u++) v[u] = __ldg(hs + (size_t)s[u] * 16 + c);
#pragma unroll
        for (int u = 0; u < 4; u++) H2ADD(aA, aB, v[u]);
    }
    for (; j < cnt; j++) {
        int s0 = __ldg(&g_csrc[base + j]);
        uint2 v0 = __ldg(hs + (size_t)s0 * 16 + c);
        H2ADD(aA, aB, v0);
    }

    float s = g_dinv[row];
    float4 bb = __ldg((const float4*)b2 + c);
    float4 v;
    v.x = fmaf(aA.x, s, bb.x);
    v.y = fmaf(aA.y, s, bb.y);
    v.z = fmaf(aB.x, s, bb.z);
    v.w = fmaf(aB.y, s, bb.w);

    float ss = v.x * v.x + v.y * v.y + v.z * v.z + v.w * v.w;
#pragma unroll
    for (int o = 8; o > 0; o >>= 1) ss += __shfl_xor_sync(0xffffffffu, ss, o);
    float sc = 1.0f / fmaxf(sqrtf(ss), 1e-12f);
    v.x *= sc; v.y *= sc; v.z *= sc; v.w *= sc;
    out[(size_t)row * 16 + c] = v;
}

// ---------------- warm-up + device pointer cache + pipeline resources ----------------
static const size_t kSmem1 = (size_t)(INF * HIDP + 128 * 65) * sizeof(float);   // 86528
static const size_t kSmem2 = (size_t)(HID * OUTF + 128 * 101) * sizeof(float);  // 77312

static unsigned int* p_h1u  = nullptr;
static uint2*        p_a1p  = nullptr;
static unsigned int* p_hs2u = nullptr;
static cudaStream_t s1;
static cudaEvent_t ev_fork, ev_g1, ev_csr, ev_join;

namespace {
struct ModulePreload {
    ModulePreload() {
        setenv("CUDA_MODULE_LOADING", "EAGER", 1);
        cudaFuncSetAttribute(k_gemm1, cudaFuncAttributeMaxDynamicSharedMemorySize, (int)kSmem1);
        cudaFuncSetAttribute(k_gemm2, cudaFuncAttributeMaxDynamicSharedMemorySize, (int)kSmem2);

        cudaStreamCreateWithFlags(&s1, cudaStreamNonBlocking);
        cudaEventCreateWithFlags(&ev_fork, cudaEventDisableTiming);
        cudaEventCreateWithFlags(&ev_g1,   cudaEventDisableTiming);
        cudaEventCreateWithFlags(&ev_csr,  cudaEventDisableTiming);
        cudaEventCreateWithFlags(&ev_join, cudaEventDisableTiming);

        void *zi, *dv, *h1, *a1, *h2;
        cudaGetSymbolAddress(&zi, g_zero_idx);
        cudaGetSymbolAddress(&dv, g_dinv);
        cudaGetSymbolAddress(&h1, g_h1u);
        cudaGetSymbolAddress(&a1, g_a1p);
        cudaGetSymbolAddress(&h2, g_hs2u);
        p_h1u  = (unsigned int*)h1;
        p_a1p  = (uint2*)a1;
        p_hs2u = (unsigned int*)h2;

        const int*   zidx = (const int*)zi;
        const float* fdv  = (const float*)dv;

        // warm-up: one launch per kernel (commits module arena before checkpoint)
        k_zero_cnt<<<(NN + 255) / 256, 256>>>();
        k_count<<<1, 256>>>(zidx, 256);
        k_bsum<<<NB, SB>>>();
        k_bscan<<<1, 128>>>();
        k_offsets<<<NB, SB>>>();
        k_fill<<<1, 256>>>(zidx, zidx, 256);
        k_gemm1<<<1, 256, kSmem1, s1>>>(fdv, fdv);   // also warms s1
        k_gather100<<<1, 256>>>((const uint2*)p_h1u, p_a1p, fdv, 0, 8);
        k_gemm2<<<1, 256, kSmem2>>>((const uint2*)p_a1p, fdv, 0);
        k_fused_b<<<1, 256>>>((const uint2*)p_hs2u, fdv, (float4*)p_a1p);
        cudaDeviceSynchronize();
    }
};
ModulePreload g_preload;
}  // namespace

// ---------------- host ----------------
extern "C" void kernel_launch(void* const* d_in, const int* in_sizes, int n_in,
                              void* d_out, int out_size) {
    const float* x   = (const float*)d_in[0];
    const int*   ei  = (const int*)d_in[1];     // [2, E]: src then dst
    const float* W1  = (const float*)d_in[2];
    const float* b1  = (const float*)d_in[3];
    const float* W2  = (const float*)d_in[4];
    const float* b2  = (const float*)d_in[5];
    float* out = (float*)d_out;
    const int* src = ei;
    const int* dst = ei + EE;

    // Fork: GEMM1 on s1 (independent of CSR); CSR build on the capture stream.
    cudaEventRecord(ev_fork, 0);
    cudaStreamWaitEvent(s1, ev_fork, 0);
    k_gemm1<<<(NN + 127) / 128, 256, kSmem1, s1>>>(x, W1);
    cudaEventRecord(ev_g1, s1);

    k_zero_cnt<<<(NN + 255) / 256, 256>>>();
    k_count<<<(EE + 255) / 256, 256>>>(dst, EE);
    k_bsum<<<NB, SB>>>();
    k_bscan<<<1, 128>>>();
    k_offsets<<<NB, SB>>>();
    k_fill<<<(EE + 255) / 256, 256>>>(src, dst, EE);
    cudaEventRecord(ev_csr, 0);

    // s1: gather chunk B (needs h1 [in-order on s1] + CSR)
    cudaStreamWaitEvent(s1, ev_csr, 0);
    {
        int rowsB = NN - CHA;
        k_gather100<<<(rowsB * 32 + 255) / 256, 256, 0, s1>>>(
            (const uint2*)p_h1u, p_a1p, b1, CHA, NN);
    }
    cudaEventRecord(ev_join, s1);

    // main: gather chunk A (needs h1 + CSR [in-order]), then GEMM2(A) overlapping gatherB
    cudaStreamWaitEvent(0, ev_g1, 0);
    k_gather100<<<(CHA * 32 + 255) / 256, 256>>>(
        (const uint2*)p_h1u, p_a1p, b1, 0, CHA);
    k_gemm2<<<CHA / 128, 256, kSmem2>>>((const uint2*)p_a1p, W2, 0);

    cudaStreamWaitEvent(0, ev_join, 0);
    k_gemm2<<<(NN - CHA + 127) / 128, 256, kSmem2>>>((const uint2*)p_a1p, W2, CHA);

    k_fused_b<<<((NN + 1) / 2 * 32 + 255) / 256, 256>>>((const uint2*)p_hs2u, b2, (float4*)out);
}

// round 14
// speedup vs baseline: 3.1561x; 1.4129x over previous
#include <cuda_runtime.h>
#include <cuda_fp16.h>
#include <cstdlib>

#define NN   50000
#define EE   800000
#define INF  128
#define HID  100
#define OUTF 64
#define SB   512
#define NB   ((NN + SB - 1) / SB)   // 98
#define CHA  25088                  // chunk-A rows (196 blocks of 128)

// -------- device scratch --------
__device__ float        g_dinv[NN];
__device__ unsigned int g_h1u[NN * 50];    // h1 = x@W1 (raw), fp16 pairs
__device__ uint2        g_a1p[NN * 25];    // h1' = relu(agg*dinv+b1), fp16
__device__ unsigned int g_hs2u[NN * 32];   // hs2 = (h1'@W2)*dinv, fp16 pairs
__device__ int          g_cnt[NN];
__device__ int          g_off[NN];
__device__ int          g_cur[NN];
__device__ int          g_csrc[EE];
__device__ int          g_bsum[NB];
__device__ int          g_bpre[NB];
__device__ int          g_zero_idx[256];   // stays zero (warm-up indices)

// ---------------- mma helpers ----------------
__device__ __forceinline__ void ldsm_x4(unsigned &r0, unsigned &r1, unsigned &r2, unsigned &r3,
                                        unsigned addr) {
    asm volatile("ldmatrix.sync.aligned.m8n8.x4.shared.b16 {%0,%1,%2,%3},[%4];\n"
                 : "=r"(r0), "=r"(r1), "=r"(r2), "=r"(r3) : "r"(addr));
}
__device__ __forceinline__ void ldsm_x4t(unsigned &r0, unsigned &r1, unsigned &r2, unsigned &r3,
                                         unsigned addr) {
    asm volatile("ldmatrix.sync.aligned.m8n8.x4.trans.shared.b16 {%0,%1,%2,%3},[%4];\n"
                 : "=r"(r0), "=r"(r1), "=r"(r2), "=r"(r3) : "r"(addr));
}
__device__ __forceinline__ void ldsm_x2t(unsigned &r0, unsigned &r1, unsigned addr) {
    asm volatile("ldmatrix.sync.aligned.m8n8.x2.trans.shared.b16 {%0,%1},[%2];\n"
                 : "=r"(r0), "=r"(r1) : "r"(addr));
}
__device__ __forceinline__ void mma16816(float* d, unsigned a0, unsigned a1, unsigned a2,
                                         unsigned a3, unsigned b0, unsigned b1) {
    asm volatile("mma.sync.aligned.m16n8k16.row.col.f32.f16.f16.f32 "
                 "{%0,%1,%2,%3},{%4,%5,%6,%7},{%8,%9},{%0,%1,%2,%3};\n"
                 : "+f"(d[0]), "+f"(d[1]), "+f"(d[2]), "+f"(d[3])
                 : "r"(a0), "r"(a1), "r"(a2), "r"(a3), "r"(b0), "r"(b1));
}

// ---------------- CSR build ----------------
__global__ void k_zero_cnt() {
    int i = blockIdx.x * blockDim.x + threadIdx.x;
    if (i < NN) g_cnt[i] = 0;
}

__global__ void k_count(const int* __restrict__ dst, int ne) {
    int e = blockIdx.x * blockDim.x + threadIdx.x;
    if (e < ne) atomicAdd(&g_cnt[dst[e]], 1);
}

__global__ __launch_bounds__(SB) void k_bsum() {
    __shared__ int sh[SB];
    int t = threadIdx.x;
    int i = blockIdx.x * SB + t;
    sh[t] = (i < NN) ? g_cnt[i] : 0;
    __syncthreads();
#pragma unroll
    for (int o = SB / 2; o > 0; o >>= 1) {
        if (t < o) sh[t] += sh[t + o];
        __syncthreads();
    }
    if (t == 0) g_bsum[blockIdx.x] = sh[0];
}

__global__ __launch_bounds__(128) void k_bscan() {
    __shared__ int sh[128];
    int t = threadIdx.x;
    int v = (t < NB) ? g_bsum[t] : 0;
    sh[t] = v;
    __syncthreads();
#pragma unroll
    for (int o = 1; o < 128; o <<= 1) {
        int u = (t >= o) ? sh[t - o] : 0;
        __syncthreads();
        sh[t] += u;
        __syncthreads();
    }
    if (t < NB) g_bpre[t] = sh[t] - v;
}

__global__ __launch_bounds__(SB) void k_offsets() {
    __shared__ int sh[SB];
    int b = blockIdx.x, t = threadIdx.x;
    int i = b * SB + t;
    int c = (i < NN) ? g_cnt[i] : 0;
    sh[t] = c;
    __syncthreads();
#pragma unroll
    for (int o = 1; o < SB; o <<= 1) {
        int u = (t >= o) ? sh[t - o] : 0;
        __syncthreads();
        sh[t] += u;
        __syncthreads();
    }
    if (i < NN) {
        int off = g_bpre[b] + sh[t] - c;
        g_off[i] = off;
        g_cur[i] = off;
        g_dinv[i] = rsqrtf((float)(c + 1));
    }
}

__global__ void k_fill(const int* __restrict__ src, const int* __restrict__ dst, int ne) {
    int e = blockIdx.x * blockDim.x + threadIdx.x;
    if (e < ne) {
        int pos = atomicAdd(&g_cur[dst[e]], 1);
        g_csrc[pos] = src[e];
    }
}

// ---------------- GEMM1 (mma fp16): h1 = x @ W1 -> fp16 ----------------
// 8 warps; warp w = 16-row m-tile; 13 n-tiles (N padded 100->104); 8 k-steps.
// sX [128][136 halves] (conflict-free ldmatrix), sW [128][104 halves].
__global__ __launch_bounds__(256) void k_gemm1(const float* __restrict__ x,
                                               const float* __restrict__ W1) {
    extern __shared__ __half smh[];
    __half* sX = smh;                  // 128*136
    __half* sW = smh + 128 * 136;      // 128*104

    const int tid = threadIdx.x;
    const int lane = tid & 31;
    const int w = tid >> 5;
    const int row0 = blockIdx.x * 128;

    const float4* x4 = (const float4*)x;
    for (int i = tid; i < 128 * 32; i += 256) {
        int r = i >> 5, q = i & 31;
        int row = row0 + r;
        float4 v = make_float4(0.f, 0.f, 0.f, 0.f);
        if (row < NN) v = x4[(size_t)row * 32 + q];
        __half2 h0 = __floats2half2_rn(v.x, v.y);
        __half2 h1 = __floats2half2_rn(v.z, v.w);
        uint2 u;
        u.x = *(unsigned*)&h0;
        u.y = *(unsigned*)&h1;
        *(uint2*)&sX[r * 136 + q * 4] = u;
    }
    for (int i = tid; i < 128 * 104; i += 256) {
        int k = i / 104, c = i - k * 104;
        sW[i] = __float2half((c < HID) ? W1[k * HID + c] : 0.0f);
    }
    __syncthreads();

    float acc[13][4];
#pragma unroll
    for (int j = 0; j < 13; j++)
#pragma unroll
        for (int q = 0; q < 4; q++) acc[j][q] = 0.0f;

    unsigned sXb = (unsigned)__cvta_generic_to_shared(sX);
    unsigned sWb = (unsigned)__cvta_generic_to_shared(sW);
    unsigned aBase = sXb + (((w * 16 + (lane & 15)) * 136) + (lane >> 4) * 8) * 2;
    int kB = lane & 15;
    int cB = 8 * (lane >> 4);

#pragma unroll
    for (int ks = 0; ks < 8; ks++) {
        unsigned a0, a1, a2, a3;
        ldsm_x4(a0, a1, a2, a3, aBase + ks * 32);
#pragma unroll
        for (int j = 0; j < 6; j++) {
            unsigned b0, b1, b2, b3;
            ldsm_x4t(b0, b1, b2, b3, sWb + ((ks * 16 + kB) * 104 + 16 * j + cB) * 2);
            mma16816(acc[2 * j],     a0, a1, a2, a3, b0, b1);
            mma16816(acc[2 * j + 1], a0, a1, a2, a3, b2, b3);
        }
        {
            unsigned b0, b1;
            ldsm_x2t(b0, b1, sWb + ((ks * 16 + kB) * 104 + 96) * 2);
            mma16816(acc[12], a0, a1, a2, a3, b0, b1);
        }
    }

    // epilogue: fp16 staging (stride 104), then coalesced uint writes
    __syncthreads();
    __half* stg = sX;
    int grp = lane >> 2, qd = lane & 3;
#pragma unroll
    for (int j = 0; j < 13; j++) {
        __half2 lo = __floats2half2_rn(acc[j][0], acc[j][1]);
        __half2 hi = __floats2half2_rn(acc[j][2], acc[j][3]);
        *(__half2*)&stg[(w * 16 + grp)     * 104 + 8 * j + 2 * qd] = lo;
        *(__half2*)&stg[(w * 16 + grp + 8) * 104 + 8 * j + 2 * qd] = hi;
    }
    __syncthreads();
    const unsigned* stgu = (const unsigned*)stg;   // stride 52 uints
    for (int i = tid; i < 128 * 50; i += 256) {
        int r = i / 50, q = i - r * 50;
        int row = row0 + r;
        if (row < NN) g_h1u[row * 50 + q] = stgu[r * 52 + q];
    }
}

// ------- gather1: h1'[r] = relu((dinv[r]*h1[r] + sum dinv[s]*h1[s]) + b1) -> fp16 -------
#define H2FMA(accA, accB, u2, s) {                                   \
    float2 _a = __half22float2(*(__half2*)&(u2).x);                  \
    float2 _b = __half22float2(*(__half2*)&(u2).y);                  \
    accA.x = fmaf(_a.x, s, accA.x); accA.y = fmaf(_a.y, s, accA.y);  \
    accB.x = fmaf(_b.x, s, accB.x); accB.y = fmaf(_b.y, s, accB.y); }

__global__ __launch_bounds__(256) void k_gather100(const uint2* __restrict__ h,
                                                   uint2* __restrict__ a1p,
                                                   const float* __restrict__ b1,
                                                   int r0, int rend) {
    int row = r0 + ((blockIdx.x * blockDim.x + threadIdx.x) >> 5);
    int lane = threadIdx.x & 31;
    if (row >= rend || lane >= 25) return;
    int base = g_off[row];
    int cnt  = g_cnt[row];

    float2 aA = make_float2(0.f, 0.f), aB = make_float2(0.f, 0.f);
    float dvr = g_dinv[row];
    {
        uint2 rv = __ldg(h + (size_t)row * 25 + lane);
        H2FMA(aA, aB, rv, dvr);
    }
    int j = 0;
    for (; j + 8 <= cnt; j += 8) {
        int s[8];
#pragma unroll
        for (int u = 0; u < 8; u++) s[u] = __ldg(&g_csrc[base + j + u]);
        uint2 v[8]; float dv[8];
#pragma unroll
        for (int u = 0; u < 8; u++) { v[u] = __ldg(h + (size_t)s[u] * 25 + lane); dv[u] = __ldg(&g_dinv[s[u]]); }
#pragma unroll
        for (int u = 0; u < 8; u++) H2FMA(aA, aB, v[u], dv[u]);
    }
    for (; j + 4 <= cnt; j += 4) {
        int s[4];
#pragma unroll
        for (int u = 0; u < 4; u++) s[u] = __ldg(&g_csrc[base + j + u]);
        uint2 v[4]; float dv[4];
#pragma unroll
        for (int u = 0; u < 4; u++) { v[u] = __ldg(h + (size_t)s[u] * 25 + lane); dv[u] = __ldg(&g_dinv[s[u]]); }
#pragma unroll
        for (int u = 0; u < 4; u++) H2FMA(aA, aB, v[u], dv[u]);
    }
    for (; j < cnt; j++) {
        int s0 = __ldg(&g_csrc[base + j]);
        uint2 v0 = __ldg(h + (size_t)s0 * 25 + lane);
        float dv0 = __ldg(&g_dinv[s0]);
        H2FMA(aA, aB, v0, dv0);
    }

    float4 bb = __ldg((const float4*)b1 + lane);
    __half2 h0 = __floats2half2_rn(fmaxf(fmaf(aA.x, dvr, bb.x), 0.0f),
                                   fmaxf(fmaf(aA.y, dvr, bb.y), 0.0f));
    __half2 h1v = __floats2half2_rn(fmaxf(fmaf(aB.x, dvr, bb.z), 0.0f),
                                    fmaxf(fmaf(aB.y, dvr, bb.w), 0.0f));
    uint2 o;
    o.x = *(unsigned*)&h0;
    o.y = *(unsigned*)&h1v;
    a1p[(size_t)row * 25 + lane] = o;
}

// ---------------- GEMM2 (mma fp16): hs2 = (h1' @ W2) * dinv -> fp16 ----------------
// K padded 100->112 (7 k-steps); 8 n-tiles. sH [128][120], sW2 [112][72].
__global__ __launch_bounds__(256) void k_gemm2(const uint2* __restrict__ a1p,
                                               const float* __restrict__ W2,
                                               int row0base) {
    extern __shared__ __half smh[];
    __half* sH = smh;                  // 128*120
    __half* sW = smh + 128 * 120;      // 112*72

    const int tid = threadIdx.x;
    const int lane = tid & 31;
    const int w = tid >> 5;
    const int row0 = row0base + blockIdx.x * 128;

    for (int i = tid; i < 128 * 25; i += 256) {
        int r = i / 25, q = i - r * 25;
        int row = row0 + r;
        uint2 u = make_uint2(0u, 0u);
        if (row < NN) u = __ldg(a1p + (size_t)row * 25 + q);
        *(uint2*)&sH[r * 120 + q * 4] = u;
    }
    for (int i = tid; i < 128 * 6; i += 256) {       // zero pad cols 100..111
        int r = i / 6, q = i - r * 6;
        ((unsigned*)sH)[r * 60 + 50 + q] = 0u;
    }
    for (int i = tid; i < 112 * 64; i += 256) {
        int k = i >> 6, c = i & 63;
        sW[k * 72 + c] = __float2half((k < HID) ? W2[k * OUTF + c] : 0.0f);
    }
    __syncthreads();

    float acc[8][4];
#pragma unroll
    for (int j = 0; j < 8; j++)
#pragma unroll
        for (int q = 0; q < 4; q++) acc[j][q] = 0.0f;

    unsigned sHb = (unsigned)__cvta_generic_to_shared(sH);
    unsigned sWb = (unsigned)__cvta_generic_to_shared(sW);
    unsigned aBase = sHb + (((w * 16 + (lane & 15)) * 120) + (lane >> 4) * 8) * 2;
    int kB = lane & 15;
    int cB = 8 * (lane >> 4);

#pragma unroll
    for (int ks = 0; ks < 7; ks++) {
        unsigned a0, a1, a2, a3;
        ldsm_x4(a0, a1, a2, a3, aBase + ks * 32);
#pragma unroll
        for (int j = 0; j < 4; j++) {
            unsigned b0, b1, b2, b3;
            ldsm_x4t(b0, b1, b2, b3, sWb + ((ks * 16 + kB) * 72 + 16 * j + cB) * 2);
            mma16816(acc[2 * j],     a0, a1, a2, a3, b0, b1);
            mma16816(acc[2 * j + 1], a0, a1, a2, a3, b2, b3);
        }
    }

    // epilogue: *dinv, fp16 staging (stride 68), coalesced writes
    __syncthreads();
    int grp = lane >> 2, qd = lane & 3;
    int r1 = w * 16 + grp, r2 = r1 + 8;
    float s1v = (row0 + r1 < NN) ? g_dinv[row0 + r1] : 0.0f;
    float s2v = (row0 + r2 < NN) ? g_dinv[row0 + r2] : 0.0f;
    __half* stg = sH;
#pragma unroll
    for (int j = 0; j < 8; j++) {
        __half2 lo = __floats2half2_rn(acc[j][0] * s1v, acc[j][1] * s1v);
        __half2 hi = __floats2half2_rn(acc[j][2] * s2v, acc[j][3] * s2v);
        *(__half2*)&stg[r1 * 68 + 8 * j + 2 * qd] = lo;
        *(__half2*)&stg[r2 * 68 + 8 * j + 2 * qd] = hi;
    }
    __syncthreads();
    const unsigned* stgu = (const unsigned*)stg;   // stride 34 uints
    for (int i = tid; i < 128 * 32; i += 256) {
        int r = i >> 5, q = i & 31;
        int row = row0 + r;
        if (row < NN) g_hs2u[row * 32 + q] = stgu[r * 34 + q];
    }
}

// ---------------- fused B: gather2(fp16) -> +b2 -> L2 normalize -> out ----------------
#define H2ADD(accA, accB, u2) {                                      \
    float2 _a = __half22float2(*(__half2*)&(u2).x);                  \
    float2 _b = __half22float2(*(__half2*)&(u2).y);                  \
    accA.x += _a.x; accA.y += _a.y; accB.x += _b.x; accB.y += _b.y; }

__global__ __launch_bounds__(256) void k_fused_b(const uint2* __restrict__ hs,
                                                 const float* __restrict__ b2,
                                                 float4* __restrict__ out) {
    int w = (blockIdx.x * blockDim.x + threadIdx.x) >> 5;
    int lane = threadIdx.x & 31;
    int row = w * 2 + (lane >> 4);
    int c = lane & 15;
    if (row >= NN) return;

    float2 aA, aB;
    {
        uint2 rv = __ldg(hs + (size_t)row * 16 + c);
        aA = __half22float2(*(__half2*)&rv.x);
        aB = __half22float2(*(__half2*)&rv.y);
    }
    int base = g_off[row];
    int cnt  = g_cnt[row];
    int j = 0;
    for (; j + 8 <= cnt; j += 8) {
        int s[8];
#pragma unroll
        for (int u = 0; u < 8; u++) s[u] = __ldg(&g_csrc[base + j + u]);
        uint2 v[8];
#pragma unroll
        for (int u = 0; u < 8; u++) v[u] = __ldg(hs + (size_t)s[u] * 16 + c);
#pragma unroll
        for (int u = 0; u < 8; u++) H2ADD(aA, aB, v[u]);
    }
    for (; j + 4 <= cnt; j += 4) {
        int s[4];
#pragma unroll
        for (int u = 0; u < 4; u++) s[u] = __ldg(&g_csrc[base + j + u]);
        uint2 v[4];
#pragma unroll
        for (int u = 0; u < 4; u++) v[u] = __ldg(hs + (size_t)s[u] * 16 + c);
#pragma unroll
        for (int u = 0; u < 4; u++) H2ADD(aA, aB, v[u]);
    }
    for (; j < cnt; j++) {
        int s0 = __ldg(&g_csrc[base + j]);
        uint2 v0 = __ldg(hs + (size_t)s0 * 16 + c);
        H2ADD(aA, aB, v0);
    }

    float s = g_dinv[row];
    float4 bb = __ldg((const float4*)b2 + c);
    float4 v;
    v.x = fmaf(aA.x, s, bb.x);
    v.y = fmaf(aA.y, s, bb.y);
    v.z = fmaf(aB.x, s, bb.z);
    v.w = fmaf(aB.y, s, bb.w);

    float ss = v.x * v.x + v.y * v.y + v.z * v.z + v.w * v.w;
#pragma unroll
    for (int o = 8; o > 0; o >>= 1) ss += __shfl_xor_sync(0xffffffffu, ss, o);
    float sc = 1.0f / fmaxf(sqrtf(ss), 1e-12f);
    v.x *= sc; v.y *= sc; v.z *= sc; v.w *= sc;
    out[(size_t)row * 16 + c] = v;
}

// ---------------- warm-up + device pointer cache + pipeline resources ----------------
static const size_t kSmem1 = (size_t)(128 * 136 + 128 * 104) * 2;   // 61440
static const size_t kSmem2 = (size_t)(128 * 120 + 112 * 72) * 2;    // 46848

static unsigned int* p_h1u  = nullptr;
static uint2*        p_a1p  = nullptr;
static unsigned int* p_hs2u = nullptr;
static cudaStream_t s1;
static cudaEvent_t ev_fork, ev_g1, ev_csr, ev_join;

namespace {
struct ModulePreload {
    ModulePreload() {
        setenv("CUDA_MODULE_LOADING", "EAGER", 1);
        cudaFuncSetAttribute(k_gemm1, cudaFuncAttributeMaxDynamicSharedMemorySize, (int)kSmem1);
        cudaFuncSetAttribute(k_gemm2, cudaFuncAttributeMaxDynamicSharedMemorySize, (int)kSmem2);

        cudaStreamCreateWithFlags(&s1, cudaStreamNonBlocking);
        cudaEventCreateWithFlags(&ev_fork, cudaEventDisableTiming);
        cudaEventCreateWithFlags(&ev_g1,   cudaEventDisableTiming);
        cudaEventCreateWithFlags(&ev_csr,  cudaEventDisableTiming);
        cudaEventCreateWithFlags(&ev_join, cudaEventDisableTiming);

        void *zi, *dv, *h1, *a1, *h2;
        cudaGetSymbolAddress(&zi, g_zero_idx);
        cudaGetSymbolAddress(&dv, g_dinv);
        cudaGetSymbolAddress(&h1, g_h1u);
        cudaGetSymbolAddress(&a1, g_a1p);
        cudaGetSymbolAddress(&h2, g_hs2u);
        p_h1u  = (unsigned int*)h1;
        p_a1p  = (uint2*)a1;
        p_hs2u = (unsigned int*)h2;

        const int*   zidx = (const int*)zi;
        const float* fdv  = (const float*)dv;
        const float* fbig = (const float*)a1;   // 10 MB readable scratch

        // warm-up: one launch per kernel (commits module arena before checkpoint)
        k_zero_cnt<<<(NN + 255) / 256, 256>>>();
        k_count<<<1, 256>>>(zidx, 256);
        k_bsum<<<NB, SB>>>();
        k_bscan<<<1, 128>>>();
        k_offsets<<<NB, SB>>>();
        k_fill<<<1, 256>>>(zidx, zidx, 256);
        k_gemm1<<<1, 256, kSmem1, s1>>>(fbig, fbig);   // also warms s1
        k_gather100<<<1, 256>>>((const uint2*)p_h1u, p_a1p, fdv, 0, 8);
        k_gemm2<<<1, 256, kSmem2>>>((const uint2*)p_a1p, fbig, 0);
        k_fused_b<<<1, 256>>>((const uint2*)p_hs2u, fdv, (float4*)p_a1p);
        cudaDeviceSynchronize();
    }
};
ModulePreload g_preload;
}  // namespace

// ---------------- host ----------------
extern "C" void kernel_launch(void* const* d_in, const int* in_sizes, int n_in,
                              void* d_out, int out_size) {
    const float* x   = (const float*)d_in[0];
    const int*   ei  = (const int*)d_in[1];     // [2, E]: src then dst
    const float* W1  = (const float*)d_in[2];
    const float* b1  = (const float*)d_in[3];
    const float* W2  = (const float*)d_in[4];
    const float* b2  = (const float*)d_in[5];
    float* out = (float*)d_out;
    const int* src = ei;
    const int* dst = ei + EE;

    // Fork: GEMM1 on s1 (independent of CSR); CSR build on the capture stream.
    cudaEventRecord(ev_fork, 0);
    cudaStreamWaitEvent(s1, ev_fork, 0);
    k_gemm1<<<(NN + 127) / 128, 256, kSmem1, s1>>>(x, W1);
    cudaEventRecord(ev_g1, s1);

    k_zero_cnt<<<(NN + 255) / 256, 256>>>();
    k_count<<<(EE + 255) / 256, 256>>>(dst, EE);
    k_bsum<<<NB, SB>>>();
    k_bscan<<<1, 128>>>();
    k_offsets<<<NB, SB>>>();
    k_fill<<<(EE + 255) / 256, 256>>>(src, dst, EE);
    cudaEventRecord(ev_csr, 0);

    // s1: gather chunk B (needs h1 [in-order on s1] + CSR)
    cudaStreamWaitEvent(s1, ev_csr, 0);
    {
        int rowsB = NN - CHA;
        k_gather100<<<(rowsB * 32 + 255) / 256, 256, 0, s1>>>(
            (const uint2*)p_h1u, p_a1p, b1, CHA, NN);
    }
    cudaEventRecord(ev_join, s1);

    // main: gather chunk A, then GEMM2(A) overlapping gatherB
    cudaStreamWaitEvent(0, ev_g1, 0);
    k_gather100<<<(CHA * 32 + 255) / 256, 256>>>(
        (const uint2*)p_h1u, p_a1p, b1, 0, CHA);
    k_gemm2<<<CHA / 128, 256, kSmem2>>>((const uint2*)p_a1p, W2, 0);

    cudaStreamWaitEvent(0, ev_join, 0);
    k_gemm2<<<(NN - CHA + 127) / 128, 256, kSmem2>>>((const uint2*)p_a1p, W2, CHA);

    k_fused_b<<<((NN + 1) / 2 * 32 + 255) / 256, 256>>>((const uint2*)p_hs2u, b2, (float4*)out);
}